// round 9
// baseline (speedup 1.0000x reference)
#include <cuda_runtime.h>

// EvolvingGNN: T=5, N=100000, E=1600000, D=H=64, FE=16.
//  (1) Only xs_out[-1] is consumed -> one GCN pass with the LSTM weight after 5 steps.
//  (2) (P@X)@W == P@(X@W): aggregate raw X first, apply W after -> fused triple GEMM.
//  (3) Edge MLP factors: hid = relu(A[src] + B[dst] + ea@W1c + b1).
//  (4) Edge MLP is MIO-bound (R8: L1=90%): Wc/b1/w2 register-resident (persistent warps),
//      ea via uniform LDG.128 broadcast, A/B split float4 + shfl exchange. Zero LDS.
//  (5) Cross-call invariant: g_cnt/g_aggx zeroed by tail blocks of k4.
//  Launch order: k1 lstm+deg, k2 scatter_x, k3 gemm_AB, k4 edge_mlp (profiled slot #4).
// edge_index arrives as int32 (JAX x64-disabled downgrades jnp.int64).

#define NMAX 100000

__device__ float g_Wt[64 * 64];        // final evolved weight, [k][r]
__device__ int   g_cnt[NMAX];          // in-degree (excl self loop); zeroed by prev call
__device__ float g_aggx[NMAX * 64];    // normAdj @ X; zeroed by prev call
__device__ float g_A[NMAX * 64];       // relu(aggx@W) @ W1[0:64]
__device__ float g_B[NMAX * 64];       // relu(aggx@W) @ W1[64:128]

__device__ __forceinline__ float sigmoidf(float x) { return 1.0f / (1.0f + expf(-x)); }

// ---------------- k1: LSTM (blocks 0..63) + in-degree histogram (blocks 64..) ----------
__global__ void lstm_deg_kernel(const float* __restrict__ w0,
                                const float* __restrict__ w_ih,
                                const float* __restrict__ w_hh,
                                const float* __restrict__ b_ih,
                                const float* __restrict__ b_hh,
                                const int* __restrict__ ei, int E) {
    if (blockIdx.x >= 64) {
        int e = (blockIdx.x - 64) * 256 + threadIdx.x;
        if (e < E) atomicAdd(&g_cnt[ei[E + e]], 1);
        return;
    }
    __shared__ float xb[64], cr[64], gate[256];
    int r = blockIdx.x;
    int tid = threadIdx.x;
    if (tid < 64) {
        xb[tid] = w0[tid * 64 + r];
        cr[tid] = 0.f;
    }
    float bsum = b_ih[tid] + b_hh[tid];
    const float4* wi = (const float4*)(w_ih + tid * 64);
    const float4* wh = (const float4*)(w_hh + tid * 64);
    for (int t = 0; t < 5; t++) {
        __syncthreads();
        float acc = bsum;
#pragma unroll
        for (int k4 = 0; k4 < 16; k4++) {
            float4 a = wi[k4];
            float4 b = wh[k4];
            float x0 = xb[4 * k4], x1 = xb[4 * k4 + 1], x2 = xb[4 * k4 + 2], x3 = xb[4 * k4 + 3];
            acc += a.x * x0 + a.y * x1 + a.z * x2 + a.w * x3;
            if (t > 0)   // hidden state == previous output column for t>=1; 0 at t==0
                acc += b.x * x0 + b.y * x1 + b.z * x2 + b.w * x3;
        }
        gate[tid] = acc;
        __syncthreads();
        if (tid < 64) {
            float gi = sigmoidf(gate[tid]);
            float gf = sigmoidf(gate[64 + tid]);
            float gg = tanhf(gate[128 + tid]);
            float go = sigmoidf(gate[192 + tid]);
            float cn = gf * cr[tid] + gi * gg;
            float hn = go * tanhf(cn);
            cr[tid] = cn;
            xb[tid] = hn;
        }
    }
    if (tid < 64) g_Wt[tid * 64 + r] = xb[tid];
}

// ---------------- k2: scatter raw X: aggx[dst] += coef * x[src]; items = E edges + N loops
__global__ void scatter_x_kernel(const float* __restrict__ x,
                                 const int* __restrict__ ei, int N, int E) {
    int idx = blockIdx.x * 256 + threadIdx.x;
    int item = idx >> 4;
    int l = idx & 15;
    int lane = threadIdx.x & 31;
    int total = E + N;
    bool active = item < total;
    int src = 0, dst = 0;
    if (active) {
        if (item < E) { src = ei[item]; dst = ei[E + item]; }
        else          { src = dst = item - E; }
    }
    float c = 0.f;
    if ((lane & 15) == 0) {
        float ps = (float)(g_cnt[src] + 1);
        float pd = (float)(g_cnt[dst] + 1);
        c = rsqrtf(ps * pd);
    }
    c = __shfl_sync(0xffffffffu, c, lane & 16);
    if (active) {
        float4 v = *(const float4*)(x + (size_t)src * 64 + 4 * l);
        atomicAdd((float4*)(g_aggx + (size_t)dst * 64 + 4 * l),
                  make_float4(c * v.x, c * v.y, c * v.z, c * v.w));
    }
}

// ---------------- k3: Y = relu(aggx @ W);  A = Y@W1a;  B = Y@W1b  (per 16-node tile) ----
__global__ void gemm_AB_kernel(const float* __restrict__ w1, int n) {
    __shared__ float Wb[64 * 64];     // reused weight buffer
    __shared__ float Xs[16 * 64];
    __shared__ float Ys[16 * 64];
    int tid = threadIdx.x;
    int row0 = blockIdx.x * 16;
    for (int i = tid; i < 4096; i += 256) Wb[i] = g_Wt[i];
    for (int i = tid; i < 1024; i += 256) {
        int rr = i >> 6, cc = i & 63;
        int nn = row0 + rr;
        Xs[i] = (nn < n) ? g_aggx[(size_t)nn * 64 + cc] : 0.f;
    }
    __syncthreads();
    int jr = (tid & 15) * 4;
    int rr = tid >> 4;
    const float* xr = Xs + rr * 64;
    {   // Y = relu(Xs @ W)
        float a0 = 0, a1 = 0, a2 = 0, a3 = 0;
#pragma unroll 8
        for (int k = 0; k < 64; k++) {
            float xv = xr[k];
            const float* wk = Wb + k * 64 + jr;
            a0 += xv * wk[0]; a1 += xv * wk[1]; a2 += xv * wk[2]; a3 += xv * wk[3];
        }
        Ys[rr * 64 + jr]     = fmaxf(a0, 0.f);
        Ys[rr * 64 + jr + 1] = fmaxf(a1, 0.f);
        Ys[rr * 64 + jr + 2] = fmaxf(a2, 0.f);
        Ys[rr * 64 + jr + 3] = fmaxf(a3, 0.f);
    }
    __syncthreads();
    for (int i = tid; i < 4096; i += 256) Wb[i] = w1[i];          // W1a
    __syncthreads();
    const float* yr = Ys + rr * 64;
    {   // A = Y @ W1a
        float a0 = 0, a1 = 0, a2 = 0, a3 = 0;
#pragma unroll 8
        for (int k = 0; k < 64; k++) {
            float yv = yr[k];
            const float* wk = Wb + k * 64 + jr;
            a0 += yv * wk[0]; a1 += yv * wk[1]; a2 += yv * wk[2]; a3 += yv * wk[3];
        }
        int nn = row0 + rr;
        if (nn < n) *(float4*)(g_A + (size_t)nn * 64 + jr) = make_float4(a0, a1, a2, a3);
    }
    __syncthreads();
    for (int i = tid; i < 4096; i += 256) Wb[i] = w1[4096 + i];   // W1b
    __syncthreads();
    {   // B = Y @ W1b
        float a0 = 0, a1 = 0, a2 = 0, a3 = 0;
#pragma unroll 8
        for (int k = 0; k < 64; k++) {
            float yv = yr[k];
            const float* wk = Wb + k * 64 + jr;
            a0 += yv * wk[0]; a1 += yv * wk[1]; a2 += yv * wk[2]; a3 += yv * wk[3];
        }
        int nn = row0 + rr;
        if (nn < n) *(float4*)(g_B + (size_t)nn * 64 + jr) = make_float4(a0, a1, a2, a3);
    }
}

// ---------------- k4 (PROFILED): Edge MLP, persistent warps, zero-LDS body --------------
// Lane layout: half = lane&15, hiB = lane>=16, j0 = half*4 + (hiB?2:0).
// Lanes 0-15 load A[src] float4 chunk, 16-31 load B[dst] chunk; shfl_xor(16) exchange.
// Wc (2 dims x 16 k), b1, w2, b2 live in registers, amortized over ~170 edges/warp.
// ea broadcast via 4 uniform LDG.128. Tail blocks zero g_cnt/g_aggx for the next call.
__global__ void edge_mlp_zero_kernel(const int* __restrict__ ei,
                                     const float* __restrict__ ea,
                                     const float* __restrict__ w1,
                                     const float* __restrict__ b1,
                                     const float* __restrict__ w2,
                                     const float* __restrict__ b2,
                                     float* __restrict__ out, int E, int N, int EB) {
    if (blockIdx.x >= EB) {
        int i = (blockIdx.x - EB) * 256 + threadIdx.x;
        if (i < N * 16) ((float4*)g_aggx)[i] = make_float4(0.f, 0.f, 0.f, 0.f);
        if (i < N) g_cnt[i] = 0;
        return;
    }
    int tid = threadIdx.x;
    int lane = tid & 31;
    int half = lane & 15;
    bool hiB = lane >= 16;
    int j0 = half * 4 + (hiB ? 2 : 0);          // this lane's two hidden dims: j0, j0+1
    float wc0[16], wc1[16];
#pragma unroll
    for (int k = 0; k < 16; k++) {
        wc0[k] = w1[8192 + k * 64 + j0];
        wc1[k] = w1[8192 + k * 64 + j0 + 1];
    }
    float bb0 = b1[j0], bb1 = b1[j0 + 1];
    float ww0 = w2[j0], ww1 = w2[j0 + 1];
    float b2v = b2[0];

    int warp = blockIdx.x * 8 + (tid >> 5);
    int nwarps = EB * 8;
    const float4* ea4 = (const float4*)ea;

    for (int e = warp; e < E; e += nwarps) {
        int src = ei[e];
        int dst = ei[E + e];
        float4 mine = hiB ? ((const float4*)g_B)[(size_t)dst * 16 + half]
                          : ((const float4*)g_A)[(size_t)src * 16 + half];
        float4 other;
        other.x = __shfl_xor_sync(0xffffffffu, mine.x, 16);
        other.y = __shfl_xor_sync(0xffffffffu, mine.y, 16);
        other.z = __shfl_xor_sync(0xffffffffu, mine.z, 16);
        other.w = __shfl_xor_sync(0xffffffffu, mine.w, 16);
        float h0, h1;
        if (hiB) {
            h0 = mine.z + other.z + bb0;
            h1 = mine.w + other.w + bb1;
        } else {
            h0 = mine.x + other.x + bb0;
            h1 = mine.y + other.y + bb1;
        }
        // ea[e] broadcast: 4 uniform float4 loads, all lanes same address
        float4 e0 = ea4[(size_t)e * 4];
        float4 e1 = ea4[(size_t)e * 4 + 1];
        float4 e2 = ea4[(size_t)e * 4 + 2];
        float4 e3 = ea4[(size_t)e * 4 + 3];
        h0 += e0.x * wc0[0] + e0.y * wc0[1] + e0.z * wc0[2] + e0.w * wc0[3];
        h1 += e0.x * wc1[0] + e0.y * wc1[1] + e0.z * wc1[2] + e0.w * wc1[3];
        h0 += e1.x * wc0[4] + e1.y * wc0[5] + e1.z * wc0[6] + e1.w * wc0[7];
        h1 += e1.x * wc1[4] + e1.y * wc1[5] + e1.z * wc1[6] + e1.w * wc1[7];
        h0 += e2.x * wc0[8] + e2.y * wc0[9] + e2.z * wc0[10] + e2.w * wc0[11];
        h1 += e2.x * wc1[8] + e2.y * wc1[9] + e2.z * wc1[10] + e2.w * wc1[11];
        h0 += e3.x * wc0[12] + e3.y * wc0[13] + e3.z * wc0[14] + e3.w * wc0[15];
        h1 += e3.x * wc1[12] + e3.y * wc1[13] + e3.z * wc1[14] + e3.w * wc1[15];
        h0 = fmaxf(h0, 0.f);
        h1 = fmaxf(h1, 0.f);
        float p = h0 * ww0 + h1 * ww1;
#pragma unroll
        for (int off = 16; off; off >>= 1) p += __shfl_xor_sync(0xffffffffu, p, off);
        if (lane == 0) out[e] = p + b2v;
    }
}

extern "C" void kernel_launch(void* const* d_in, const int* in_sizes, int n_in,
                              void* d_out, int out_size) {
    const float* xs = (const float*)d_in[0];
    const int* ei = (const int*)d_in[1];            // int32 (JAX x64 disabled)
    const float* ea = (const float*)d_in[2];
    const float* init_w = (const float*)d_in[3];
    const float* w_ih = (const float*)d_in[4];
    const float* w_hh = (const float*)d_in[5];
    const float* b_ih = (const float*)d_in[6];
    const float* b_hh = (const float*)d_in[7];
    const float* w1 = (const float*)d_in[8];
    const float* b1 = (const float*)d_in[9];
    const float* w2 = (const float*)d_in[10];
    const float* b2 = (const float*)d_in[11];
    float* out = (float*)d_out;

    int N = in_sizes[0] / (5 * 64);
    int E = in_sizes[1] / 2;

    // k1: LSTM + in-degree histogram
    lstm_deg_kernel<<<64 + (E + 255) / 256, 256>>>(init_w, w_ih, w_hh, b_ih, b_hh, ei, E);
    // k2: scatter raw X (edges + self loops)
    int items = E + N;
    scatter_x_kernel<<<(items * 16 + 255) / 256, 256>>>(xs + (size_t)4 * N * 64, ei, N, E);
    // k3: fused Y/A/B GEMMs
    gemm_AB_kernel<<<(N + 15) / 16, 256>>>(w1, N);
    // k4: per-edge MLP + logit (PROFILED, persistent) + tail zeroing for next call
    int EB = 1184;
    int ZB = (N * 16 + 255) / 256;
    edge_mlp_zero_kernel<<<EB + ZB, 256>>>(ei, ea, w1, b1, w2, b2, out, E, N, EB);
}

// round 10
// speedup vs baseline: 1.2012x; 1.2012x over previous
#include <cuda_runtime.h>

// EvolvingGNN: T=5, N=100000, E=1600000, D=H=64, FE=16.
//  (1) Only xs_out[-1] is consumed -> one GCN pass with the LSTM weight after 5 steps.
//  (2) (P@X)@W == P@(X@W): aggregate raw X first, apply W after -> fused triple GEMM.
//  (3) Edge MLP factors: hid = relu(A[src] + B[dst] + ea@W1c + b1).
//  (4) Edge MLP is LATENCY-bound (R9: no pipe >35%): 2-edge ILP unroll + contiguous
//      per-warp edge chunks; Wc/b1/w2 register-resident; zero LDS.
//  (5) Cross-call invariant: g_cnt/g_aggx zeroed by tail blocks of k4.
//  Launch order: k1 lstm+deg, k2 scatter_x, k3 gemm_AB, k4 edge_mlp (profiled slot #4).
// edge_index arrives as int32 (JAX x64-disabled downgrades jnp.int64).

#define NMAX 100000

__device__ float g_Wt[64 * 64];        // final evolved weight, [k][r]
__device__ int   g_cnt[NMAX];          // in-degree (excl self loop); zeroed by prev call
__device__ float g_aggx[NMAX * 64];    // normAdj @ X; zeroed by prev call
__device__ float g_A[NMAX * 64];       // relu(aggx@W) @ W1[0:64]
__device__ float g_B[NMAX * 64];       // relu(aggx@W) @ W1[64:128]

__device__ __forceinline__ float sigmoidf(float x) { return 1.0f / (1.0f + expf(-x)); }

// ---------------- k1: LSTM (blocks 0..63) + in-degree histogram (blocks 64..) ----------
__global__ void lstm_deg_kernel(const float* __restrict__ w0,
                                const float* __restrict__ w_ih,
                                const float* __restrict__ w_hh,
                                const float* __restrict__ b_ih,
                                const float* __restrict__ b_hh,
                                const int* __restrict__ ei, int E) {
    if (blockIdx.x >= 64) {
        int e = (blockIdx.x - 64) * 256 + threadIdx.x;
        if (e < E) atomicAdd(&g_cnt[ei[E + e]], 1);
        return;
    }
    __shared__ float xb[64], cr[64], gate[256];
    int r = blockIdx.x;
    int tid = threadIdx.x;
    if (tid < 64) {
        xb[tid] = w0[tid * 64 + r];
        cr[tid] = 0.f;
    }
    float bsum = b_ih[tid] + b_hh[tid];
    const float4* wi = (const float4*)(w_ih + tid * 64);
    const float4* wh = (const float4*)(w_hh + tid * 64);
    for (int t = 0; t < 5; t++) {
        __syncthreads();
        float acc = bsum;
#pragma unroll
        for (int k4 = 0; k4 < 16; k4++) {
            float4 a = wi[k4];
            float4 b = wh[k4];
            float x0 = xb[4 * k4], x1 = xb[4 * k4 + 1], x2 = xb[4 * k4 + 2], x3 = xb[4 * k4 + 3];
            acc += a.x * x0 + a.y * x1 + a.z * x2 + a.w * x3;
            if (t > 0)   // hidden state == previous output column for t>=1; 0 at t==0
                acc += b.x * x0 + b.y * x1 + b.z * x2 + b.w * x3;
        }
        gate[tid] = acc;
        __syncthreads();
        if (tid < 64) {
            float gi = sigmoidf(gate[tid]);
            float gf = sigmoidf(gate[64 + tid]);
            float gg = tanhf(gate[128 + tid]);
            float go = sigmoidf(gate[192 + tid]);
            float cn = gf * cr[tid] + gi * gg;
            float hn = go * tanhf(cn);
            cr[tid] = cn;
            xb[tid] = hn;
        }
    }
    if (tid < 64) g_Wt[tid * 64 + r] = xb[tid];
}

// ---------------- k2: scatter raw X: aggx[dst] += coef * x[src]; items = E edges + N loops
__global__ void scatter_x_kernel(const float* __restrict__ x,
                                 const int* __restrict__ ei, int N, int E) {
    int idx = blockIdx.x * 256 + threadIdx.x;
    int item = idx >> 4;
    int l = idx & 15;
    int lane = threadIdx.x & 31;
    int total = E + N;
    bool active = item < total;
    int src = 0, dst = 0;
    if (active) {
        if (item < E) { src = ei[item]; dst = ei[E + item]; }
        else          { src = dst = item - E; }
    }
    float c = 0.f;
    if ((lane & 15) == 0) {
        float ps = (float)(g_cnt[src] + 1);
        float pd = (float)(g_cnt[dst] + 1);
        c = rsqrtf(ps * pd);
    }
    c = __shfl_sync(0xffffffffu, c, lane & 16);
    if (active) {
        float4 v = *(const float4*)(x + (size_t)src * 64 + 4 * l);
        atomicAdd((float4*)(g_aggx + (size_t)dst * 64 + 4 * l),
                  make_float4(c * v.x, c * v.y, c * v.z, c * v.w));
    }
}

// ---------------- k3: Y = relu(aggx @ W);  A = Y@W1a;  B = Y@W1b  (per 16-node tile) ----
__global__ void gemm_AB_kernel(const float* __restrict__ w1, int n) {
    __shared__ float Wb[64 * 64];     // reused weight buffer
    __shared__ float Xs[16 * 64];
    __shared__ float Ys[16 * 64];
    int tid = threadIdx.x;
    int row0 = blockIdx.x * 16;
    for (int i = tid; i < 4096; i += 256) Wb[i] = g_Wt[i];
    for (int i = tid; i < 1024; i += 256) {
        int rr = i >> 6, cc = i & 63;
        int nn = row0 + rr;
        Xs[i] = (nn < n) ? g_aggx[(size_t)nn * 64 + cc] : 0.f;
    }
    __syncthreads();
    int jr = (tid & 15) * 4;
    int rr = tid >> 4;
    const float* xr = Xs + rr * 64;
    {   // Y = relu(Xs @ W)
        float a0 = 0, a1 = 0, a2 = 0, a3 = 0;
#pragma unroll 8
        for (int k = 0; k < 64; k++) {
            float xv = xr[k];
            const float* wk = Wb + k * 64 + jr;
            a0 += xv * wk[0]; a1 += xv * wk[1]; a2 += xv * wk[2]; a3 += xv * wk[3];
        }
        Ys[rr * 64 + jr]     = fmaxf(a0, 0.f);
        Ys[rr * 64 + jr + 1] = fmaxf(a1, 0.f);
        Ys[rr * 64 + jr + 2] = fmaxf(a2, 0.f);
        Ys[rr * 64 + jr + 3] = fmaxf(a3, 0.f);
    }
    __syncthreads();
    for (int i = tid; i < 4096; i += 256) Wb[i] = w1[i];          // W1a
    __syncthreads();
    const float* yr = Ys + rr * 64;
    {   // A = Y @ W1a
        float a0 = 0, a1 = 0, a2 = 0, a3 = 0;
#pragma unroll 8
        for (int k = 0; k < 64; k++) {
            float yv = yr[k];
            const float* wk = Wb + k * 64 + jr;
            a0 += yv * wk[0]; a1 += yv * wk[1]; a2 += yv * wk[2]; a3 += yv * wk[3];
        }
        int nn = row0 + rr;
        if (nn < n) *(float4*)(g_A + (size_t)nn * 64 + jr) = make_float4(a0, a1, a2, a3);
    }
    __syncthreads();
    for (int i = tid; i < 4096; i += 256) Wb[i] = w1[4096 + i];   // W1b
    __syncthreads();
    {   // B = Y @ W1b
        float a0 = 0, a1 = 0, a2 = 0, a3 = 0;
#pragma unroll 8
        for (int k = 0; k < 64; k++) {
            float yv = yr[k];
            const float* wk = Wb + k * 64 + jr;
            a0 += yv * wk[0]; a1 += yv * wk[1]; a2 += yv * wk[2]; a3 += yv * wk[3];
        }
        int nn = row0 + rr;
        if (nn < n) *(float4*)(g_B + (size_t)nn * 64 + jr) = make_float4(a0, a1, a2, a3);
    }
}

// ---------------- k4 (PROFILED): Edge MLP, 2-edge ILP, contiguous chunks ----------------
// Lane layout: half = lane&15, hiB = lane>=16, j0 = half*4 + (hiB?2:0).
// Lanes 0-15 load A[src] float4 chunk, 16-31 load B[dst] chunk; shfl_xor(16) exchange.
// Wc (2 dims x 16 k), b1, w2, b2 in registers. ea via uniform LDG.128 broadcast.
// Each warp owns a CONTIGUOUS edge range and processes 2 edges per iteration (ILP).
__global__ void edge_mlp_zero_kernel(const int* __restrict__ ei,
                                     const float* __restrict__ ea,
                                     const float* __restrict__ w1,
                                     const float* __restrict__ b1,
                                     const float* __restrict__ w2,
                                     const float* __restrict__ b2,
                                     float* __restrict__ out, int E, int N, int EB) {
    if (blockIdx.x >= EB) {
        int i = (blockIdx.x - EB) * 256 + threadIdx.x;
        if (i < N * 16) ((float4*)g_aggx)[i] = make_float4(0.f, 0.f, 0.f, 0.f);
        if (i < N) g_cnt[i] = 0;
        return;
    }
    int tid = threadIdx.x;
    int lane = tid & 31;
    int half = lane & 15;
    bool hiB = lane >= 16;
    int j0 = half * 4 + (hiB ? 2 : 0);          // this lane's two hidden dims: j0, j0+1
    float wc0[16], wc1[16];
#pragma unroll
    for (int k = 0; k < 16; k++) {
        wc0[k] = w1[8192 + k * 64 + j0];
        wc1[k] = w1[8192 + k * 64 + j0 + 1];
    }
    float bb0 = b1[j0], bb1 = b1[j0 + 1];
    float ww0 = w2[j0], ww1 = w2[j0 + 1];
    float b2v = b2[0];

    int warp = blockIdx.x * 8 + (tid >> 5);
    int nwarps = EB * 8;
    int chunk = (E + nwarps - 1) / nwarps;
    int eBeg = warp * chunk;
    int eEnd = eBeg + chunk;
    if (eEnd > E) eEnd = E;
    const float4* ea4 = (const float4*)ea;
    const float4* A4 = (const float4*)g_A;
    const float4* B4 = (const float4*)g_B;

    for (int e = eBeg; e < eEnd; e += 2) {
        bool two = (e + 1 < eEnd);
        int eb = two ? e + 1 : e;
        // ---- issue ALL loads for both edges up front ----
        int srcA = ei[e],  dstA = ei[E + e];
        int srcB = ei[eb], dstB = ei[E + eb];
        float4 mA = hiB ? B4[(size_t)dstA * 16 + half] : A4[(size_t)srcA * 16 + half];
        float4 mB = hiB ? B4[(size_t)dstB * 16 + half] : A4[(size_t)srcB * 16 + half];
        float4 a0v = ea4[(size_t)e * 4];
        float4 a1v = ea4[(size_t)e * 4 + 1];
        float4 a2v = ea4[(size_t)e * 4 + 2];
        float4 a3v = ea4[(size_t)e * 4 + 3];
        float4 c0v = ea4[(size_t)eb * 4];
        float4 c1v = ea4[(size_t)eb * 4 + 1];
        float4 c2v = ea4[(size_t)eb * 4 + 2];
        float4 c3v = ea4[(size_t)eb * 4 + 3];
        // ---- exchange ----
        float4 oA, oB;
        oA.x = __shfl_xor_sync(0xffffffffu, mA.x, 16);
        oA.y = __shfl_xor_sync(0xffffffffu, mA.y, 16);
        oA.z = __shfl_xor_sync(0xffffffffu, mA.z, 16);
        oA.w = __shfl_xor_sync(0xffffffffu, mA.w, 16);
        oB.x = __shfl_xor_sync(0xffffffffu, mB.x, 16);
        oB.y = __shfl_xor_sync(0xffffffffu, mB.y, 16);
        oB.z = __shfl_xor_sync(0xffffffffu, mB.z, 16);
        oB.w = __shfl_xor_sync(0xffffffffu, mB.w, 16);
        float h0A, h1A, h0B, h1B;
        if (hiB) {
            h0A = mA.z + oA.z + bb0;  h1A = mA.w + oA.w + bb1;
            h0B = mB.z + oB.z + bb0;  h1B = mB.w + oB.w + bb1;
        } else {
            h0A = mA.x + oA.x + bb0;  h1A = mA.y + oA.y + bb1;
            h0B = mB.x + oB.x + bb0;  h1B = mB.y + oB.y + bb1;
        }
        // ---- ea @ Wc, both edges ----
        h0A += a0v.x * wc0[0]  + a0v.y * wc0[1]  + a0v.z * wc0[2]  + a0v.w * wc0[3]
             + a1v.x * wc0[4]  + a1v.y * wc0[5]  + a1v.z * wc0[6]  + a1v.w * wc0[7]
             + a2v.x * wc0[8]  + a2v.y * wc0[9]  + a2v.z * wc0[10] + a2v.w * wc0[11]
             + a3v.x * wc0[12] + a3v.y * wc0[13] + a3v.z * wc0[14] + a3v.w * wc0[15];
        h1A += a0v.x * wc1[0]  + a0v.y * wc1[1]  + a0v.z * wc1[2]  + a0v.w * wc1[3]
             + a1v.x * wc1[4]  + a1v.y * wc1[5]  + a1v.z * wc1[6]  + a1v.w * wc1[7]
             + a2v.x * wc1[8]  + a2v.y * wc1[9]  + a2v.z * wc1[10] + a2v.w * wc1[11]
             + a3v.x * wc1[12] + a3v.y * wc1[13] + a3v.z * wc1[14] + a3v.w * wc1[15];
        h0B += c0v.x * wc0[0]  + c0v.y * wc0[1]  + c0v.z * wc0[2]  + c0v.w * wc0[3]
             + c1v.x * wc0[4]  + c1v.y * wc0[5]  + c1v.z * wc0[6]  + c1v.w * wc0[7]
             + c2v.x * wc0[8]  + c2v.y * wc0[9]  + c2v.z * wc0[10] + c2v.w * wc0[11]
             + c3v.x * wc0[12] + c3v.y * wc0[13] + c3v.z * wc0[14] + c3v.w * wc0[15];
        h1B += c0v.x * wc1[0]  + c0v.y * wc1[1]  + c0v.z * wc1[2]  + c0v.w * wc1[3]
             + c1v.x * wc1[4]  + c1v.y * wc1[5]  + c1v.z * wc1[6]  + c1v.w * wc1[7]
             + c2v.x * wc1[8]  + c2v.y * wc1[9]  + c2v.z * wc1[10] + c2v.w * wc1[11]
             + c3v.x * wc1[12] + c3v.y * wc1[13] + c3v.z * wc1[14] + c3v.w * wc1[15];
        float pA = fmaxf(h0A, 0.f) * ww0 + fmaxf(h1A, 0.f) * ww1;
        float pB = fmaxf(h0B, 0.f) * ww0 + fmaxf(h1B, 0.f) * ww1;
#pragma unroll
        for (int off = 16; off; off >>= 1) {
            pA += __shfl_xor_sync(0xffffffffu, pA, off);
            pB += __shfl_xor_sync(0xffffffffu, pB, off);
        }
        if (lane == 0) {
            out[e] = pA + b2v;
            if (two) out[eb] = pB + b2v;
        }
    }
}

extern "C" void kernel_launch(void* const* d_in, const int* in_sizes, int n_in,
                              void* d_out, int out_size) {
    const float* xs = (const float*)d_in[0];
    const int* ei = (const int*)d_in[1];            // int32 (JAX x64 disabled)
    const float* ea = (const float*)d_in[2];
    const float* init_w = (const float*)d_in[3];
    const float* w_ih = (const float*)d_in[4];
    const float* w_hh = (const float*)d_in[5];
    const float* b_ih = (const float*)d_in[6];
    const float* b_hh = (const float*)d_in[7];
    const float* w1 = (const float*)d_in[8];
    const float* b1 = (const float*)d_in[9];
    const float* w2 = (const float*)d_in[10];
    const float* b2 = (const float*)d_in[11];
    float* out = (float*)d_out;

    int N = in_sizes[0] / (5 * 64);
    int E = in_sizes[1] / 2;

    // k1: LSTM + in-degree histogram
    lstm_deg_kernel<<<64 + (E + 255) / 256, 256>>>(init_w, w_ih, w_hh, b_ih, b_hh, ei, E);
    // k2: scatter raw X (edges + self loops)
    int items = E + N;
    scatter_x_kernel<<<(items * 16 + 255) / 256, 256>>>(xs + (size_t)4 * N * 64, ei, N, E);
    // k3: fused Y/A/B GEMMs
    gemm_AB_kernel<<<(N + 15) / 16, 256>>>(w1, N);
    // k4: per-edge MLP + logit (PROFILED, persistent 2-edge ILP) + tail zeroing
    int EB = 1184;
    int ZB = (N * 16 + 255) / 256;
    edge_mlp_zero_kernel<<<EB + ZB, 256>>>(ei, ea, w1, b1, w2, b2, out, E, N, EB);
}

// round 12
// speedup vs baseline: 1.4697x; 1.2236x over previous
#include <cuda_runtime.h>
#include <cstdint>

// EvolvingGNN: T=5, N=100000, E=1600000, D=H=64, FE=16.
//  (1) Only xs_out[-1] is consumed -> one GCN pass with the LSTM weight after 5 steps.
//  (2) (P@X)@W == P@(X@W): aggregate raw X first, apply W after -> fused triple GEMM.
//  (3) Edge MLP factors: hid = relu(A[src] + B[dst] + ea@W1c + b1).
//  (4) Edge MLP (latency-bound on streamed ea/ei): cp.async double-buffered smem staging
//      of ea + src/dst per 128-edge tile; Wc/b1/w2 register-resident; 2-edge ILP.
//  (5) Cross-call invariant: g_cnt/g_aggx zeroed by tail blocks of k4.
//  Launch order: k1 lstm+deg, k2 scatter_x, k3 gemm_AB, k4 edge_mlp (profiled slot #4).
// edge_index arrives as int32 (JAX x64-disabled downgrades jnp.int64).

#define NMAX 100000
#define ECHUNK 2048
#define ETILE 128
// smem buffer layout per tile: [0,8192) ea (128 edges x 64B); [8192,8704) src; [8704,9216) dst
#define BUFSZ 9216

__device__ float g_Wt[64 * 64];        // final evolved weight, [k][r]
__device__ int   g_cnt[NMAX];          // in-degree (excl self loop); zeroed by prev call
__device__ float g_aggx[NMAX * 64];    // normAdj @ X; zeroed by prev call
__device__ float g_A[NMAX * 64];       // relu(aggx@W) @ W1[0:64]
__device__ float g_B[NMAX * 64];       // relu(aggx@W) @ W1[64:128]

__device__ __forceinline__ float sigmoidf(float x) { return 1.0f / (1.0f + expf(-x)); }

__device__ __forceinline__ void cp_async16(unsigned int smem, const void* gmem, bool pred) {
    asm volatile(
        "{\n\t.reg .pred p;\n\tsetp.ne.b32 p, %2, 0;\n\t"
        "@p cp.async.cg.shared.global [%0], [%1], 16;\n\t}"
        :: "r"(smem), "l"(gmem), "r"((int)pred) : "memory");
}

// ---------------- k1: LSTM (blocks 0..63) + in-degree histogram (blocks 64..) ----------
__global__ void lstm_deg_kernel(const float* __restrict__ w0,
                                const float* __restrict__ w_ih,
                                const float* __restrict__ w_hh,
                                const float* __restrict__ b_ih,
                                const float* __restrict__ b_hh,
                                const int* __restrict__ ei, int E) {
    if (blockIdx.x >= 64) {
        int e = (blockIdx.x - 64) * 256 + threadIdx.x;
        if (e < E) atomicAdd(&g_cnt[ei[E + e]], 1);
        return;
    }
    __shared__ float xb[64], cr[64], gate[256];
    int r = blockIdx.x;
    int tid = threadIdx.x;
    if (tid < 64) {
        xb[tid] = w0[tid * 64 + r];
        cr[tid] = 0.f;
    }
    float bsum = b_ih[tid] + b_hh[tid];
    const float4* wi = (const float4*)(w_ih + tid * 64);
    const float4* wh = (const float4*)(w_hh + tid * 64);
    for (int t = 0; t < 5; t++) {
        __syncthreads();
        float acc = bsum;
#pragma unroll
        for (int k4 = 0; k4 < 16; k4++) {
            float4 a = wi[k4];
            float4 b = wh[k4];
            float x0 = xb[4 * k4], x1 = xb[4 * k4 + 1], x2 = xb[4 * k4 + 2], x3 = xb[4 * k4 + 3];
            acc += a.x * x0 + a.y * x1 + a.z * x2 + a.w * x3;
            if (t > 0)   // hidden state == previous output column for t>=1; 0 at t==0
                acc += b.x * x0 + b.y * x1 + b.z * x2 + b.w * x3;
        }
        gate[tid] = acc;
        __syncthreads();
        if (tid < 64) {
            float gi = sigmoidf(gate[tid]);
            float gf = sigmoidf(gate[64 + tid]);
            float gg = tanhf(gate[128 + tid]);
            float go = sigmoidf(gate[192 + tid]);
            float cn = gf * cr[tid] + gi * gg;
            float hn = go * tanhf(cn);
            cr[tid] = cn;
            xb[tid] = hn;
        }
    }
    if (tid < 64) g_Wt[tid * 64 + r] = xb[tid];
}

// ---------------- k2: scatter raw X: aggx[dst] += coef * x[src]; items = E edges + N loops
__global__ void scatter_x_kernel(const float* __restrict__ x,
                                 const int* __restrict__ ei, int N, int E) {
    int idx = blockIdx.x * 256 + threadIdx.x;
    int item = idx >> 4;
    int l = idx & 15;
    int lane = threadIdx.x & 31;
    int total = E + N;
    bool active = item < total;
    int src = 0, dst = 0;
    if (active) {
        if (item < E) { src = ei[item]; dst = ei[E + item]; }
        else          { src = dst = item - E; }
    }
    float c = 0.f;
    if ((lane & 15) == 0) {
        float ps = (float)(g_cnt[src] + 1);
        float pd = (float)(g_cnt[dst] + 1);
        c = rsqrtf(ps * pd);
    }
    c = __shfl_sync(0xffffffffu, c, lane & 16);
    if (active) {
        float4 v = *(const float4*)(x + (size_t)src * 64 + 4 * l);
        atomicAdd((float4*)(g_aggx + (size_t)dst * 64 + 4 * l),
                  make_float4(c * v.x, c * v.y, c * v.z, c * v.w));
    }
}

// ---------------- k3: Y = relu(aggx @ W);  A = Y@W1a;  B = Y@W1b  (per 16-node tile) ----
__global__ void gemm_AB_kernel(const float* __restrict__ w1, int n) {
    __shared__ float Wb[64 * 64];     // reused weight buffer
    __shared__ float Xs[16 * 64];
    __shared__ float Ys[16 * 64];
    int tid = threadIdx.x;
    int row0 = blockIdx.x * 16;
    for (int i = tid; i < 4096; i += 256) Wb[i] = g_Wt[i];
    for (int i = tid; i < 1024; i += 256) {
        int rr = i >> 6, cc = i & 63;
        int nn = row0 + rr;
        Xs[i] = (nn < n) ? g_aggx[(size_t)nn * 64 + cc] : 0.f;
    }
    __syncthreads();
    int jr = (tid & 15) * 4;
    int rr = tid >> 4;
    const float* xr = Xs + rr * 64;
    {   // Y = relu(Xs @ W)
        float a0 = 0, a1 = 0, a2 = 0, a3 = 0;
#pragma unroll 8
        for (int k = 0; k < 64; k++) {
            float xv = xr[k];
            const float* wk = Wb + k * 64 + jr;
            a0 += xv * wk[0]; a1 += xv * wk[1]; a2 += xv * wk[2]; a3 += xv * wk[3];
        }
        Ys[rr * 64 + jr]     = fmaxf(a0, 0.f);
        Ys[rr * 64 + jr + 1] = fmaxf(a1, 0.f);
        Ys[rr * 64 + jr + 2] = fmaxf(a2, 0.f);
        Ys[rr * 64 + jr + 3] = fmaxf(a3, 0.f);
    }
    __syncthreads();
    for (int i = tid; i < 4096; i += 256) Wb[i] = w1[i];          // W1a
    __syncthreads();
    const float* yr = Ys + rr * 64;
    {   // A = Y @ W1a
        float a0 = 0, a1 = 0, a2 = 0, a3 = 0;
#pragma unroll 8
        for (int k = 0; k < 64; k++) {
            float yv = yr[k];
            const float* wk = Wb + k * 64 + jr;
            a0 += yv * wk[0]; a1 += yv * wk[1]; a2 += yv * wk[2]; a3 += yv * wk[3];
        }
        int nn = row0 + rr;
        if (nn < n) *(float4*)(g_A + (size_t)nn * 64 + jr) = make_float4(a0, a1, a2, a3);
    }
    __syncthreads();
    for (int i = tid; i < 4096; i += 256) Wb[i] = w1[4096 + i];   // W1b
    __syncthreads();
    {   // B = Y @ W1b
        float a0 = 0, a1 = 0, a2 = 0, a3 = 0;
#pragma unroll 8
        for (int k = 0; k < 64; k++) {
            float yv = yr[k];
            const float* wk = Wb + k * 64 + jr;
            a0 += yv * wk[0]; a1 += yv * wk[1]; a2 += yv * wk[2]; a3 += yv * wk[3];
        }
        int nn = row0 + rr;
        if (nn < n) *(float4*)(g_B + (size_t)nn * 64 + jr) = make_float4(a0, a1, a2, a3);
    }
}

// ---------------- k4 (PROFILED): Edge MLP with cp.async-staged ea/src/dst ---------------
// Each block owns a contiguous ECHUNK-edge range; double-buffered ETILE=128-edge tiles.
// Lane handles hidden dims 2*lane, 2*lane+1 for each edge; 2-edge ILP per iteration.
// A/B fp32 gathers (float2/lane) hidden by occupancy + ILP. Wc/b1/w2 in registers.
__global__ void edge_mlp_zero_kernel(const int* __restrict__ ei,
                                     const float* __restrict__ ea,
                                     const float* __restrict__ w1,
                                     const float* __restrict__ b1,
                                     const float* __restrict__ w2,
                                     const float* __restrict__ b2,
                                     float* __restrict__ out, int E, int N, int EB) {
    if (blockIdx.x >= EB) {
        int i = (blockIdx.x - EB) * 256 + threadIdx.x;
        if (i < N * 16) ((float4*)g_aggx)[i] = make_float4(0.f, 0.f, 0.f, 0.f);
        if (i < N) g_cnt[i] = 0;
        return;
    }
    __shared__ __align__(16) char sbuf[2][BUFSZ];
    int tid = threadIdx.x;
    int lane = tid & 31;
    int wid = tid >> 5;

    // register-resident Wc (2 hidden dims per lane), b1, w2, b2
    int j0 = 2 * lane;
    float wc0[16], wc1[16];
#pragma unroll
    for (int k = 0; k < 16; k++) {
        wc0[k] = w1[8192 + k * 64 + j0];
        wc1[k] = w1[8192 + k * 64 + j0 + 1];
    }
    float bb0 = b1[j0], bb1 = b1[j0 + 1];
    float ww0 = w2[j0], ww1 = w2[j0 + 1];
    float b2v = b2[0];

    int chunkBase = blockIdx.x * ECHUNK;
    int rem = E - chunkBase;
    if (rem <= 0) return;
    int nt = (rem < ECHUNK ? rem : ECHUNK);
    nt = (nt + ETILE - 1) / ETILE;

    const float4* ea4 = (const float4*)ea;

    // stage a tile: all 256 threads
    auto stage = [&](int buf, int e0) {
        unsigned int sb = (unsigned int)__cvta_generic_to_shared(sbuf[buf]);
#pragma unroll
        for (int k = 0; k < 2; k++) {
            int t = tid * 2 + k;                          // 0..511 float4 slots
            long gidx = (long)e0 * 4 + t;
            cp_async16(sb + t * 16, ea4 + gidx, gidx < (long)E * 4);
        }
        if (tid < 32) {
            int gi = e0 + tid * 4;
            cp_async16(sb + 8192 + tid * 16, ei + gi, gi < E);
        } else if (tid < 64) {
            int t = tid - 32;
            int gi = e0 + t * 4;
            cp_async16(sb + 8704 + t * 16, ei + E + gi, gi < E);
        }
    };

    stage(0, chunkBase);
    asm volatile("cp.async.commit_group;" ::: "memory");

    for (int t = 0; t < nt; t++) {
        if (t + 1 < nt) stage((t + 1) & 1, chunkBase + (t + 1) * ETILE);
        asm volatile("cp.async.commit_group;" ::: "memory");
        asm volatile("cp.async.wait_group 1;" ::: "memory");
        __syncthreads();

        const char* sb = sbuf[t & 1];
        const float4* eaS = (const float4*)sb;
        const int* srcS = (const int*)(sb + 8192);
        const int* dstS = (const int*)(sb + 8704);
        int eTile = chunkBase + t * ETILE;
        int rBase = wid * 16;
#pragma unroll 2
        for (int i = 0; i < 16; i += 2) {
            int r = rBase + i;
            int e = eTile + r;
            if (e >= E) break;
            int2 sAB = *(const int2*)(srcS + r);
            int2 dAB = *(const int2*)(dstS + r);
            // gathers for both edges, issued up front
            float2 avA = *(const float2*)(g_A + (size_t)sAB.x * 64 + j0);
            float2 bvA = *(const float2*)(g_B + (size_t)dAB.x * 64 + j0);
            float2 avB = *(const float2*)(g_A + (size_t)sAB.y * 64 + j0);
            float2 bvB = *(const float2*)(g_B + (size_t)dAB.y * 64 + j0);
            // ea from smem (uniform broadcast)
            float4 a0v = eaS[r * 4],     a1v = eaS[r * 4 + 1];
            float4 a2v = eaS[r * 4 + 2], a3v = eaS[r * 4 + 3];
            float4 c0v = eaS[r * 4 + 4], c1v = eaS[r * 4 + 5];
            float4 c2v = eaS[r * 4 + 6], c3v = eaS[r * 4 + 7];
            float h0A = avA.x + bvA.x + bb0;
            float h1A = avA.y + bvA.y + bb1;
            float h0B = avB.x + bvB.x + bb0;
            float h1B = avB.y + bvB.y + bb1;
            h0A += a0v.x * wc0[0]  + a0v.y * wc0[1]  + a0v.z * wc0[2]  + a0v.w * wc0[3]
                 + a1v.x * wc0[4]  + a1v.y * wc0[5]  + a1v.z * wc0[6]  + a1v.w * wc0[7]
                 + a2v.x * wc0[8]  + a2v.y * wc0[9]  + a2v.z * wc0[10] + a2v.w * wc0[11]
                 + a3v.x * wc0[12] + a3v.y * wc0[13] + a3v.z * wc0[14] + a3v.w * wc0[15];
            h1A += a0v.x * wc1[0]  + a0v.y * wc1[1]  + a0v.z * wc1[2]  + a0v.w * wc1[3]
                 + a1v.x * wc1[4]  + a1v.y * wc1[5]  + a1v.z * wc1[6]  + a1v.w * wc1[7]
                 + a2v.x * wc1[8]  + a2v.y * wc1[9]  + a2v.z * wc1[10] + a2v.w * wc1[11]
                 + a3v.x * wc1[12] + a3v.y * wc1[13] + a3v.z * wc1[14] + a3v.w * wc1[15];
            h0B += c0v.x * wc0[0]  + c0v.y * wc0[1]  + c0v.z * wc0[2]  + c0v.w * wc0[3]
                 + c1v.x * wc0[4]  + c1v.y * wc0[5]  + c1v.z * wc0[6]  + c1v.w * wc0[7]
                 + c2v.x * wc0[8]  + c2v.y * wc0[9]  + c2v.z * wc0[10] + c2v.w * wc0[11]
                 + c3v.x * wc0[12] + c3v.y * wc0[13] + c3v.z * wc0[14] + c3v.w * wc0[15];
            h1B += c0v.x * wc1[0]  + c0v.y * wc1[1]  + c0v.z * wc1[2]  + c0v.w * wc1[3]
                 + c1v.x * wc1[4]  + c1v.y * wc1[5]  + c1v.z * wc1[6]  + c1v.w * wc1[7]
                 + c2v.x * wc1[8]  + c2v.y * wc1[9]  + c2v.z * wc1[10] + c2v.w * wc1[11]
                 + c3v.x * wc1[12] + c3v.y * wc1[13] + c3v.z * wc1[14] + c3v.w * wc1[15];
            float pA = fmaxf(h0A, 0.f) * ww0 + fmaxf(h1A, 0.f) * ww1;
            float pB = fmaxf(h0B, 0.f) * ww0 + fmaxf(h1B, 0.f) * ww1;
#pragma unroll
            for (int off = 16; off; off >>= 1) {
                pA += __shfl_xor_sync(0xffffffffu, pA, off);
                pB += __shfl_xor_sync(0xffffffffu, pB, off);
            }
            if (lane == 0) {
                out[e] = pA + b2v;
                if (e + 1 < E) out[e + 1] = pB + b2v;
            }
        }
        __syncthreads();
    }
}

extern "C" void kernel_launch(void* const* d_in, const int* in_sizes, int n_in,
                              void* d_out, int out_size) {
    const float* xs = (const float*)d_in[0];
    const int* ei = (const int*)d_in[1];            // int32 (JAX x64 disabled)
    const float* ea = (const float*)d_in[2];
    const float* init_w = (const float*)d_in[3];
    const float* w_ih = (const float*)d_in[4];
    const float* w_hh = (const float*)d_in[5];
    const float* b_ih = (const float*)d_in[6];
    const float* b_hh = (const float*)d_in[7];
    const float* w1 = (const float*)d_in[8];
    const float* b1 = (const float*)d_in[9];
    const float* w2 = (const float*)d_in[10];
    const float* b2 = (const float*)d_in[11];
    float* out = (float*)d_out;

    int N = in_sizes[0] / (5 * 64);
    int E = in_sizes[1] / 2;

    // k1: LSTM + in-degree histogram
    lstm_deg_kernel<<<64 + (E + 255) / 256, 256>>>(init_w, w_ih, w_hh, b_ih, b_hh, ei, E);
    // k2: scatter raw X (edges + self loops)
    int items = E + N;
    scatter_x_kernel<<<(items * 16 + 255) / 256, 256>>>(xs + (size_t)4 * N * 64, ei, N, E);
    // k3: fused Y/A/B GEMMs
    gemm_AB_kernel<<<(N + 15) / 16, 256>>>(w1, N);
    // k4: per-edge MLP + logit (PROFILED, cp.async pipeline) + tail zeroing
    int EB = (E + ECHUNK - 1) / ECHUNK;
    int ZB = (N * 16 + 255) / 256;
    edge_mlp_zero_kernel<<<EB + ZB, 256>>>(ei, ea, w1, b1, w2, b2, out, E, N, EB);
}

// round 13
// speedup vs baseline: 1.5652x; 1.0650x over previous
#include <cuda_runtime.h>
#include <cuda_fp16.h>
#include <cstdint>

// EvolvingGNN: T=5, N=100000, E=1600000, D=H=64, FE=16.
//  (1) Only xs_out[-1] is consumed -> one GCN pass with the LSTM weight after 5 steps.
//  (2) (P@X)@W == P@(X@W): aggregate raw X first, apply W after -> fused triple GEMM.
//  (3) Edge MLP factors: hid = relu(A[src] + B[dst] + ea@W1c + b1).
//  (4) Edge MLP: cp.async-staged ea/ei + fp16 A/B tables (one 128B line per gather),
//      Wc/b1/w2 register-resident, 2-edge ILP, launch_bounds(256,4) for occupancy.
//  (5) Cross-call invariant: g_cnt/g_aggx zeroed by tail blocks of k4.
//  Launch order: k1 lstm+deg, k2 scatter_x, k3 gemm_AB, k4 edge_mlp (profiled slot #4).
// edge_index arrives as int32 (JAX x64-disabled downgrades jnp.int64).

#define NMAX 100000
#define ECHUNK 1024
#define ETILE 128
// smem buffer layout per tile: [0,8192) ea (128 edges x 64B); [8192,8704) src; [8704,9216) dst
#define BUFSZ 9216

__device__ float  g_Wt[64 * 64];       // final evolved weight, [k][r]
__device__ int    g_cnt[NMAX];         // in-degree (excl self loop); zeroed by prev call
__device__ float  g_aggx[NMAX * 64];   // normAdj @ X; zeroed by prev call
__device__ __half g_A[NMAX * 64];      // fp16: relu(aggx@W) @ W1[0:64]
__device__ __half g_B[NMAX * 64];      // fp16: relu(aggx@W) @ W1[64:128]

__device__ __forceinline__ float sigmoidf(float x) { return 1.0f / (1.0f + expf(-x)); }

__device__ __forceinline__ void cp_async16(unsigned int smem, const void* gmem, bool pred) {
    asm volatile(
        "{\n\t.reg .pred p;\n\tsetp.ne.b32 p, %2, 0;\n\t"
        "@p cp.async.cg.shared.global [%0], [%1], 16;\n\t}"
        :: "r"(smem), "l"(gmem), "r"((int)pred) : "memory");
}

// ---------------- k1: LSTM (blocks 0..63) + in-degree histogram (blocks 64..) ----------
__global__ void lstm_deg_kernel(const float* __restrict__ w0,
                                const float* __restrict__ w_ih,
                                const float* __restrict__ w_hh,
                                const float* __restrict__ b_ih,
                                const float* __restrict__ b_hh,
                                const int* __restrict__ ei, int E) {
    if (blockIdx.x >= 64) {
        int e = (blockIdx.x - 64) * 256 + threadIdx.x;
        if (e < E) atomicAdd(&g_cnt[ei[E + e]], 1);
        return;
    }
    __shared__ float xb[64], cr[64], gate[256];
    int r = blockIdx.x;
    int tid = threadIdx.x;
    if (tid < 64) {
        xb[tid] = w0[tid * 64 + r];
        cr[tid] = 0.f;
    }
    float bsum = b_ih[tid] + b_hh[tid];
    const float4* wi = (const float4*)(w_ih + tid * 64);
    const float4* wh = (const float4*)(w_hh + tid * 64);
    for (int t = 0; t < 5; t++) {
        __syncthreads();
        float acc = bsum;
#pragma unroll
        for (int k4 = 0; k4 < 16; k4++) {
            float4 a = wi[k4];
            float4 b = wh[k4];
            float x0 = xb[4 * k4], x1 = xb[4 * k4 + 1], x2 = xb[4 * k4 + 2], x3 = xb[4 * k4 + 3];
            acc += a.x * x0 + a.y * x1 + a.z * x2 + a.w * x3;
            if (t > 0)   // hidden state == previous output column for t>=1; 0 at t==0
                acc += b.x * x0 + b.y * x1 + b.z * x2 + b.w * x3;
        }
        gate[tid] = acc;
        __syncthreads();
        if (tid < 64) {
            float gi = sigmoidf(gate[tid]);
            float gf = sigmoidf(gate[64 + tid]);
            float gg = tanhf(gate[128 + tid]);
            float go = sigmoidf(gate[192 + tid]);
            float cn = gf * cr[tid] + gi * gg;
            float hn = go * tanhf(cn);
            cr[tid] = cn;
            xb[tid] = hn;
        }
    }
    if (tid < 64) g_Wt[tid * 64 + r] = xb[tid];
}

// ---------------- k2: scatter raw X: aggx[dst] += coef * x[src]; items = E edges + N loops
__global__ void scatter_x_kernel(const float* __restrict__ x,
                                 const int* __restrict__ ei, int N, int E) {
    int idx = blockIdx.x * 256 + threadIdx.x;
    int item = idx >> 4;
    int l = idx & 15;
    int lane = threadIdx.x & 31;
    int total = E + N;
    bool active = item < total;
    int src = 0, dst = 0;
    if (active) {
        if (item < E) { src = ei[item]; dst = ei[E + item]; }
        else          { src = dst = item - E; }
    }
    float c = 0.f;
    if ((lane & 15) == 0) {
        float ps = (float)(g_cnt[src] + 1);
        float pd = (float)(g_cnt[dst] + 1);
        c = rsqrtf(ps * pd);
    }
    c = __shfl_sync(0xffffffffu, c, lane & 16);
    if (active) {
        float4 v = *(const float4*)(x + (size_t)src * 64 + 4 * l);
        atomicAdd((float4*)(g_aggx + (size_t)dst * 64 + 4 * l),
                  make_float4(c * v.x, c * v.y, c * v.z, c * v.w));
    }
}

// ---------------- k3: Y = relu(aggx @ W);  A = Y@W1a;  B = Y@W1b  -> fp16 stores --------
__global__ void gemm_AB_kernel(const float* __restrict__ w1, int n) {
    __shared__ float Wb[64 * 64];     // reused weight buffer
    __shared__ float Xs[16 * 64];
    __shared__ float Ys[16 * 64];
    int tid = threadIdx.x;
    int row0 = blockIdx.x * 16;
    for (int i = tid; i < 4096; i += 256) Wb[i] = g_Wt[i];
    for (int i = tid; i < 1024; i += 256) {
        int rr = i >> 6, cc = i & 63;
        int nn = row0 + rr;
        Xs[i] = (nn < n) ? g_aggx[(size_t)nn * 64 + cc] : 0.f;
    }
    __syncthreads();
    int jr = (tid & 15) * 4;
    int rr = tid >> 4;
    const float* xr = Xs + rr * 64;
    {   // Y = relu(Xs @ W)
        float a0 = 0, a1 = 0, a2 = 0, a3 = 0;
#pragma unroll 8
        for (int k = 0; k < 64; k++) {
            float xv = xr[k];
            const float* wk = Wb + k * 64 + jr;
            a0 += xv * wk[0]; a1 += xv * wk[1]; a2 += xv * wk[2]; a3 += xv * wk[3];
        }
        Ys[rr * 64 + jr]     = fmaxf(a0, 0.f);
        Ys[rr * 64 + jr + 1] = fmaxf(a1, 0.f);
        Ys[rr * 64 + jr + 2] = fmaxf(a2, 0.f);
        Ys[rr * 64 + jr + 3] = fmaxf(a3, 0.f);
    }
    __syncthreads();
    for (int i = tid; i < 4096; i += 256) Wb[i] = w1[i];          // W1a
    __syncthreads();
    const float* yr = Ys + rr * 64;
    {   // A = Y @ W1a -> fp16
        float a0 = 0, a1 = 0, a2 = 0, a3 = 0;
#pragma unroll 8
        for (int k = 0; k < 64; k++) {
            float yv = yr[k];
            const float* wk = Wb + k * 64 + jr;
            a0 += yv * wk[0]; a1 += yv * wk[1]; a2 += yv * wk[2]; a3 += yv * wk[3];
        }
        int nn = row0 + rr;
        if (nn < n) {
            __half2 h01 = __floats2half2_rn(a0, a1);
            __half2 h23 = __floats2half2_rn(a2, a3);
            *(uint2*)(g_A + (size_t)nn * 64 + jr) =
                make_uint2(*(unsigned*)&h01, *(unsigned*)&h23);
        }
    }
    __syncthreads();
    for (int i = tid; i < 4096; i += 256) Wb[i] = w1[4096 + i];   // W1b
    __syncthreads();
    {   // B = Y @ W1b -> fp16
        float a0 = 0, a1 = 0, a2 = 0, a3 = 0;
#pragma unroll 8
        for (int k = 0; k < 64; k++) {
            float yv = yr[k];
            const float* wk = Wb + k * 64 + jr;
            a0 += yv * wk[0]; a1 += yv * wk[1]; a2 += yv * wk[2]; a3 += yv * wk[3];
        }
        int nn = row0 + rr;
        if (nn < n) {
            __half2 h01 = __floats2half2_rn(a0, a1);
            __half2 h23 = __floats2half2_rn(a2, a3);
            *(uint2*)(g_B + (size_t)nn * 64 + jr) =
                make_uint2(*(unsigned*)&h01, *(unsigned*)&h23);
        }
    }
}

// ---------------- k4 (PROFILED): Edge MLP, cp.async-staged ea/ei, fp16 A/B gathers ------
__global__ void __launch_bounds__(256, 4)
edge_mlp_zero_kernel(const int* __restrict__ ei,
                     const float* __restrict__ ea,
                     const float* __restrict__ w1,
                     const float* __restrict__ b1,
                     const float* __restrict__ w2,
                     const float* __restrict__ b2,
                     float* __restrict__ out, int E, int N, int EB) {
    if (blockIdx.x >= EB) {
        int i = (blockIdx.x - EB) * 256 + threadIdx.x;
        if (i < N * 16) ((float4*)g_aggx)[i] = make_float4(0.f, 0.f, 0.f, 0.f);
        if (i < N) g_cnt[i] = 0;
        return;
    }
    __shared__ __align__(16) char sbuf[2][BUFSZ];
    int tid = threadIdx.x;
    int lane = tid & 31;
    int wid = tid >> 5;

    // register-resident Wc (2 hidden dims per lane), b1, w2, b2
    int j0 = 2 * lane;
    float wc0[16], wc1[16];
#pragma unroll
    for (int k = 0; k < 16; k++) {
        wc0[k] = w1[8192 + k * 64 + j0];
        wc1[k] = w1[8192 + k * 64 + j0 + 1];
    }
    float bb0 = b1[j0], bb1 = b1[j0 + 1];
    float ww0 = w2[j0], ww1 = w2[j0 + 1];
    float b2v = b2[0];

    int chunkBase = blockIdx.x * ECHUNK;
    int rem = E - chunkBase;
    if (rem <= 0) return;
    int nt = (rem < ECHUNK ? rem : ECHUNK);
    nt = (nt + ETILE - 1) / ETILE;

    const float4* ea4 = (const float4*)ea;

    // stage a tile: all 256 threads
    auto stage = [&](int buf, int e0) {
        unsigned int sb = (unsigned int)__cvta_generic_to_shared(sbuf[buf]);
#pragma unroll
        for (int k = 0; k < 2; k++) {
            int t = tid * 2 + k;                          // 0..511 float4 slots
            long gidx = (long)e0 * 4 + t;
            cp_async16(sb + t * 16, ea4 + gidx, gidx < (long)E * 4);
        }
        if (tid < 32) {
            int gi = e0 + tid * 4;
            cp_async16(sb + 8192 + tid * 16, ei + gi, gi < E);
        } else if (tid < 64) {
            int t = tid - 32;
            int gi = e0 + t * 4;
            cp_async16(sb + 8704 + t * 16, ei + E + gi, gi < E);
        }
    };

    stage(0, chunkBase);
    asm volatile("cp.async.commit_group;" ::: "memory");

    for (int t = 0; t < nt; t++) {
        if (t + 1 < nt) stage((t + 1) & 1, chunkBase + (t + 1) * ETILE);
        asm volatile("cp.async.commit_group;" ::: "memory");
        asm volatile("cp.async.wait_group 1;" ::: "memory");
        __syncthreads();

        const char* sb = sbuf[t & 1];
        const float4* eaS = (const float4*)sb;
        const int* srcS = (const int*)(sb + 8192);
        const int* dstS = (const int*)(sb + 8704);
        int eTile = chunkBase + t * ETILE;
        int rBase = wid * 16;
#pragma unroll 2
        for (int i = 0; i < 16; i += 2) {
            int r = rBase + i;
            int e = eTile + r;
            if (e >= E) break;
            int2 sAB = *(const int2*)(srcS + r);
            int2 dAB = *(const int2*)(dstS + r);
            // fp16 gathers for both edges, issued up front (4B each)
            __half2 avA = *(const __half2*)(g_A + (size_t)sAB.x * 64 + j0);
            __half2 bvA = *(const __half2*)(g_B + (size_t)dAB.x * 64 + j0);
            __half2 avB = *(const __half2*)(g_A + (size_t)sAB.y * 64 + j0);
            __half2 bvB = *(const __half2*)(g_B + (size_t)dAB.y * 64 + j0);
            // ea from smem (uniform broadcast)
            float4 a0v = eaS[r * 4],     a1v = eaS[r * 4 + 1];
            float4 a2v = eaS[r * 4 + 2], a3v = eaS[r * 4 + 3];
            float4 c0v = eaS[r * 4 + 4], c1v = eaS[r * 4 + 5];
            float4 c2v = eaS[r * 4 + 6], c3v = eaS[r * 4 + 7];
            float2 fA = __half22float2(avA), gA = __half22float2(bvA);
            float2 fB = __half22float2(avB), gB = __half22float2(bvB);
            float h0A = fA.x + gA.x + bb0;
            float h1A = fA.y + gA.y + bb1;
            float h0B = fB.x + gB.x + bb0;
            float h1B = fB.y + gB.y + bb1;
            h0A += a0v.x * wc0[0]  + a0v.y * wc0[1]  + a0v.z * wc0[2]  + a0v.w * wc0[3]
                 + a1v.x * wc0[4]  + a1v.y * wc0[5]  + a1v.z * wc0[6]  + a1v.w * wc0[7]
                 + a2v.x * wc0[8]  + a2v.y * wc0[9]  + a2v.z * wc0[10] + a2v.w * wc0[11]
                 + a3v.x * wc0[12] + a3v.y * wc0[13] + a3v.z * wc0[14] + a3v.w * wc0[15];
            h1A += a0v.x * wc1[0]  + a0v.y * wc1[1]  + a0v.z * wc1[2]  + a0v.w * wc1[3]
                 + a1v.x * wc1[4]  + a1v.y * wc1[5]  + a1v.z * wc1[6]  + a1v.w * wc1[7]
                 + a2v.x * wc1[8]  + a2v.y * wc1[9]  + a2v.z * wc1[10] + a2v.w * wc1[11]
                 + a3v.x * wc1[12] + a3v.y * wc1[13] + a3v.z * wc1[14] + a3v.w * wc1[15];
            h0B += c0v.x * wc0[0]  + c0v.y * wc0[1]  + c0v.z * wc0[2]  + c0v.w * wc0[3]
                 + c1v.x * wc0[4]  + c1v.y * wc0[5]  + c1v.z * wc0[6]  + c1v.w * wc0[7]
                 + c2v.x * wc0[8]  + c2v.y * wc0[9]  + c2v.z * wc0[10] + c2v.w * wc0[11]
                 + c3v.x * wc0[12] + c3v.y * wc0[13] + c3v.z * wc0[14] + c3v.w * wc0[15];
            h1B += c0v.x * wc1[0]  + c0v.y * wc1[1]  + c0v.z * wc1[2]  + c0v.w * wc1[3]
                 + c1v.x * wc1[4]  + c1v.y * wc1[5]  + c1v.z * wc1[6]  + c1v.w * wc1[7]
                 + c2v.x * wc1[8]  + c2v.y * wc1[9]  + c2v.z * wc1[10] + c2v.w * wc1[11]
                 + c3v.x * wc1[12] + c3v.y * wc1[13] + c3v.z * wc1[14] + c3v.w * wc1[15];
            float pA = fmaxf(h0A, 0.f) * ww0 + fmaxf(h1A, 0.f) * ww1;
            float pB = fmaxf(h0B, 0.f) * ww0 + fmaxf(h1B, 0.f) * ww1;
#pragma unroll
            for (int off = 16; off; off >>= 1) {
                pA += __shfl_xor_sync(0xffffffffu, pA, off);
                pB += __shfl_xor_sync(0xffffffffu, pB, off);
            }
            if (lane == 0) {
                out[e] = pA + b2v;
                if (e + 1 < E) out[e + 1] = pB + b2v;
            }
        }
        __syncthreads();
    }
}

extern "C" void kernel_launch(void* const* d_in, const int* in_sizes, int n_in,
                              void* d_out, int out_size) {
    const float* xs = (const float*)d_in[0];
    const int* ei = (const int*)d_in[1];            // int32 (JAX x64 disabled)
    const float* ea = (const float*)d_in[2];
    const float* init_w = (const float*)d_in[3];
    const float* w_ih = (const float*)d_in[4];
    const float* w_hh = (const float*)d_in[5];
    const float* b_ih = (const float*)d_in[6];
    const float* b_hh = (const float*)d_in[7];
    const float* w1 = (const float*)d_in[8];
    const float* b1 = (const float*)d_in[9];
    const float* w2 = (const float*)d_in[10];
    const float* b2 = (const float*)d_in[11];
    float* out = (float*)d_out;

    int N = in_sizes[0] / (5 * 64);
    int E = in_sizes[1] / 2;

    // k1: LSTM + in-degree histogram
    lstm_deg_kernel<<<64 + (E + 255) / 256, 256>>>(init_w, w_ih, w_hh, b_ih, b_hh, ei, E);
    // k2: scatter raw X (edges + self loops)
    int items = E + N;
    scatter_x_kernel<<<(items * 16 + 255) / 256, 256>>>(xs + (size_t)4 * N * 64, ei, N, E);
    // k3: fused Y/A/B GEMMs (fp16 outputs)
    gemm_AB_kernel<<<(N + 15) / 16, 256>>>(w1, N);
    // k4: per-edge MLP + logit (PROFILED, cp.async pipeline, fp16 gathers) + tail zeroing
    int EB = (E + ECHUNK - 1) / ECHUNK;
    int ZB = (N * 16 + 255) / 256;
    edge_mlp_zero_kernel<<<EB + ZB, 256>>>(ei, ea, w1, b1, w2, b2, out, E, N, EB);
}

// round 14
// speedup vs baseline: 2.0633x; 1.3182x over previous
#include <cuda_runtime.h>
#include <cuda_fp16.h>
#include <cstdint>

// EvolvingGNN: T=5, N=100000, E=1600000, D=H=64, FE=16.
//  (1) Only xs_out[-1] is consumed -> one GCN pass with the LSTM weight after 5 steps.
//  (2) (P@X)@W == P@(X@W): aggregate raw X first, apply W after -> fused triple GEMM.
//  (3) Edge MLP factors: hid = relu(A[src] + B[dst] + ea@W1c + b1).
//  (4) Edge MLP: cp.async-staged ea/ei + fp16 A/B, register Wc, 2-edge ILP (R13: 180us).
//  (5) gemm_AB register-tiled: 64-node blocks, 4x4 outputs/thread -> FMA-floor bound.
//  (6) Cross-call invariant: g_cnt/g_aggx zeroed by tail blocks of the last kernel.
//  Launch order: k1 lstm, k2 deg, k3 scatter, k4 gemm (PROFILED slot), k5 edge_mlp.
// edge_index arrives as int32 (JAX x64-disabled downgrades jnp.int64).

#define NMAX 100000
#define ECHUNK 1024
#define ETILE 128
#define BUFSZ 9216

__device__ float  g_Wt[64 * 64];       // final evolved weight, [k][r]
__device__ int    g_cnt[NMAX];         // in-degree (excl self loop); zeroed by prev call
__device__ float  g_aggx[NMAX * 64];   // normAdj @ X; zeroed by prev call
__device__ __half g_A[NMAX * 64];      // fp16: relu(aggx@W) @ W1[0:64]
__device__ __half g_B[NMAX * 64];      // fp16: relu(aggx@W) @ W1[64:128]

__device__ __forceinline__ float sigmoidf(float x) { return 1.0f / (1.0f + expf(-x)); }

__device__ __forceinline__ void cp_async16(unsigned int smem, const void* gmem, bool pred) {
    asm volatile(
        "{\n\t.reg .pred p;\n\tsetp.ne.b32 p, %2, 0;\n\t"
        "@p cp.async.cg.shared.global [%0], [%1], 16;\n\t}"
        :: "r"(smem), "l"(gmem), "r"((int)pred) : "memory");
}

// ---------------- k1: LSTM, all 5 steps in one launch ----------------
__global__ void lstm_kernel(const float* __restrict__ w0,
                            const float* __restrict__ w_ih,
                            const float* __restrict__ w_hh,
                            const float* __restrict__ b_ih,
                            const float* __restrict__ b_hh) {
    __shared__ float xb[64], cr[64], gate[256];
    int r = blockIdx.x;
    int tid = threadIdx.x;
    if (tid < 64) {
        xb[tid] = w0[tid * 64 + r];
        cr[tid] = 0.f;
    }
    float bsum = b_ih[tid] + b_hh[tid];
    const float4* wi = (const float4*)(w_ih + tid * 64);
    const float4* wh = (const float4*)(w_hh + tid * 64);
    for (int t = 0; t < 5; t++) {
        __syncthreads();
        float acc = bsum;
#pragma unroll
        for (int k4 = 0; k4 < 16; k4++) {
            float4 a = wi[k4];
            float4 b = wh[k4];
            float x0 = xb[4 * k4], x1 = xb[4 * k4 + 1], x2 = xb[4 * k4 + 2], x3 = xb[4 * k4 + 3];
            acc += a.x * x0 + a.y * x1 + a.z * x2 + a.w * x3;
            if (t > 0)   // hidden state == previous output column for t>=1; 0 at t==0
                acc += b.x * x0 + b.y * x1 + b.z * x2 + b.w * x3;
        }
        gate[tid] = acc;
        __syncthreads();
        if (tid < 64) {
            float gi = sigmoidf(gate[tid]);
            float gf = sigmoidf(gate[64 + tid]);
            float gg = tanhf(gate[128 + tid]);
            float go = sigmoidf(gate[192 + tid]);
            float cn = gf * cr[tid] + gi * gg;
            float hn = go * tanhf(cn);
            cr[tid] = cn;
            xb[tid] = hn;
        }
    }
    if (tid < 64) g_Wt[tid * 64 + r] = xb[tid];
}

// ---------------- k2: in-degree histogram ----------------
__global__ void deg_count_kernel(const int* __restrict__ ei, int E) {
    int e = blockIdx.x * blockDim.x + threadIdx.x;
    if (e < E) atomicAdd(&g_cnt[ei[E + e]], 1);
}

// ---------------- k3: scatter raw X: aggx[dst] += coef * x[src]; E edges + N self loops -
__global__ void scatter_x_kernel(const float* __restrict__ x,
                                 const int* __restrict__ ei, int N, int E) {
    int idx = blockIdx.x * 256 + threadIdx.x;
    int item = idx >> 4;
    int l = idx & 15;
    int lane = threadIdx.x & 31;
    int total = E + N;
    bool active = item < total;
    int src = 0, dst = 0;
    if (active) {
        if (item < E) { src = ei[item]; dst = ei[E + item]; }
        else          { src = dst = item - E; }
    }
    float c = 0.f;
    if ((lane & 15) == 0) {
        float ps = (float)(g_cnt[src] + 1);
        float pd = (float)(g_cnt[dst] + 1);
        c = rsqrtf(ps * pd);
    }
    c = __shfl_sync(0xffffffffu, c, lane & 16);
    if (active) {
        float4 v = *(const float4*)(x + (size_t)src * 64 + 4 * l);
        atomicAdd((float4*)(g_aggx + (size_t)dst * 64 + 4 * l),
                  make_float4(c * v.x, c * v.y, c * v.z, c * v.w));
    }
}

// ---------------- k4 (PROFILED): register-tiled triple GEMM, 64 nodes/block -------------
// Thread (tx=tid&15, ty=tid>>4) computes a 4x4 output tile (rows 4ty.., cols 4tx..).
// Per k: 1 LDS.128 (W row chunk) + 4 scalar LDS (X col, 65-padded) + 16 FFMA.
// Stage1: Y=relu(X@W) written back into the X tile. Stages 2/3 reuse the W buffer.
__global__ void __launch_bounds__(256) gemm_AB_kernel(const float* __restrict__ w1, int n) {
    __shared__ float Xs[64][65];
    __shared__ float Ws[64][64];
    int tid = threadIdx.x;
    int tx = tid & 15, ty = tid >> 4;
    int row0 = blockIdx.x * 64;
    int jc = tx * 4;
    int rb = ty * 4;

    // load X tile (zero-padded) + W (g_Wt)
#pragma unroll
    for (int j = 0; j < 4; j++) {
        int i = tid + j * 256;            // float4 slot 0..1023
        int r = i >> 4;
        int kb = (i & 15) * 4;
        int nn = row0 + r;
        float4 v = (nn < n) ? *(const float4*)(g_aggx + (size_t)nn * 64 + kb)
                            : make_float4(0.f, 0.f, 0.f, 0.f);
        Xs[r][kb] = v.x; Xs[r][kb + 1] = v.y; Xs[r][kb + 2] = v.z; Xs[r][kb + 3] = v.w;
        ((float4*)Ws)[i] = ((const float4*)g_Wt)[i];
    }
    __syncthreads();

    float acc[4][4];
    // ---- stage 1: Y = relu(X @ W) ----
#pragma unroll
    for (int i = 0; i < 4; i++)
#pragma unroll
        for (int j = 0; j < 4; j++) acc[i][j] = 0.f;
#pragma unroll 8
    for (int k = 0; k < 64; k++) {
        float4 wv = *(const float4*)&Ws[k][jc];
        float x0 = Xs[rb][k], x1 = Xs[rb + 1][k], x2 = Xs[rb + 2][k], x3 = Xs[rb + 3][k];
        acc[0][0] += x0 * wv.x; acc[0][1] += x0 * wv.y; acc[0][2] += x0 * wv.z; acc[0][3] += x0 * wv.w;
        acc[1][0] += x1 * wv.x; acc[1][1] += x1 * wv.y; acc[1][2] += x1 * wv.z; acc[1][3] += x1 * wv.w;
        acc[2][0] += x2 * wv.x; acc[2][1] += x2 * wv.y; acc[2][2] += x2 * wv.z; acc[2][3] += x2 * wv.w;
        acc[3][0] += x3 * wv.x; acc[3][1] += x3 * wv.y; acc[3][2] += x3 * wv.z; acc[3][3] += x3 * wv.w;
    }
    __syncthreads();          // all reads of Xs/Ws done
    // write Y (relu) back into Xs; load W1a into Ws
#pragma unroll
    for (int i = 0; i < 4; i++)
#pragma unroll
        for (int j = 0; j < 4; j++) Xs[rb + i][jc + j] = fmaxf(acc[i][j], 0.f);
#pragma unroll
    for (int j = 0; j < 4; j++) {
        int i = tid + j * 256;
        ((float4*)Ws)[i] = ((const float4*)w1)[i];                 // W1a rows 0..63
    }
    __syncthreads();

    // ---- stage 2: A = Y @ W1a -> fp16 ----
#pragma unroll
    for (int i = 0; i < 4; i++)
#pragma unroll
        for (int j = 0; j < 4; j++) acc[i][j] = 0.f;
#pragma unroll 8
    for (int k = 0; k < 64; k++) {
        float4 wv = *(const float4*)&Ws[k][jc];
        float x0 = Xs[rb][k], x1 = Xs[rb + 1][k], x2 = Xs[rb + 2][k], x3 = Xs[rb + 3][k];
        acc[0][0] += x0 * wv.x; acc[0][1] += x0 * wv.y; acc[0][2] += x0 * wv.z; acc[0][3] += x0 * wv.w;
        acc[1][0] += x1 * wv.x; acc[1][1] += x1 * wv.y; acc[1][2] += x1 * wv.z; acc[1][3] += x1 * wv.w;
        acc[2][0] += x2 * wv.x; acc[2][1] += x2 * wv.y; acc[2][2] += x2 * wv.z; acc[2][3] += x2 * wv.w;
        acc[3][0] += x3 * wv.x; acc[3][1] += x3 * wv.y; acc[3][2] += x3 * wv.z; acc[3][3] += x3 * wv.w;
    }
#pragma unroll
    for (int i = 0; i < 4; i++) {
        int nn = row0 + rb + i;
        if (nn < n) {
            __half2 h01 = __floats2half2_rn(acc[i][0], acc[i][1]);
            __half2 h23 = __floats2half2_rn(acc[i][2], acc[i][3]);
            *(uint2*)(g_A + (size_t)nn * 64 + jc) =
                make_uint2(*(unsigned*)&h01, *(unsigned*)&h23);
        }
    }
    __syncthreads();          // Ws reads done
#pragma unroll
    for (int j = 0; j < 4; j++) {
        int i = tid + j * 256;
        ((float4*)Ws)[i] = ((const float4*)w1)[1024 + i];          // W1b rows 64..127
    }
    __syncthreads();

    // ---- stage 3: B = Y @ W1b -> fp16 ----
#pragma unroll
    for (int i = 0; i < 4; i++)
#pragma unroll
        for (int j = 0; j < 4; j++) acc[i][j] = 0.f;
#pragma unroll 8
    for (int k = 0; k < 64; k++) {
        float4 wv = *(const float4*)&Ws[k][jc];
        float x0 = Xs[rb][k], x1 = Xs[rb + 1][k], x2 = Xs[rb + 2][k], x3 = Xs[rb + 3][k];
        acc[0][0] += x0 * wv.x; acc[0][1] += x0 * wv.y; acc[0][2] += x0 * wv.z; acc[0][3] += x0 * wv.w;
        acc[1][0] += x1 * wv.x; acc[1][1] += x1 * wv.y; acc[1][2] += x1 * wv.z; acc[1][3] += x1 * wv.w;
        acc[2][0] += x2 * wv.x; acc[2][1] += x2 * wv.y; acc[2][2] += x2 * wv.z; acc[2][3] += x2 * wv.w;
        acc[3][0] += x3 * wv.x; acc[3][1] += x3 * wv.y; acc[3][2] += x3 * wv.z; acc[3][3] += x3 * wv.w;
    }
#pragma unroll
    for (int i = 0; i < 4; i++) {
        int nn = row0 + rb + i;
        if (nn < n) {
            __half2 h01 = __floats2half2_rn(acc[i][0], acc[i][1]);
            __half2 h23 = __floats2half2_rn(acc[i][2], acc[i][3]);
            *(uint2*)(g_B + (size_t)nn * 64 + jc) =
                make_uint2(*(unsigned*)&h01, *(unsigned*)&h23);
        }
    }
}

// ---------------- k5: Edge MLP, cp.async-staged ea/ei, fp16 A/B gathers + zero tail -----
__global__ void __launch_bounds__(256, 4)
edge_mlp_zero_kernel(const int* __restrict__ ei,
                     const float* __restrict__ ea,
                     const float* __restrict__ w1,
                     const float* __restrict__ b1,
                     const float* __restrict__ w2,
                     const float* __restrict__ b2,
                     float* __restrict__ out, int E, int N, int EB) {
    if (blockIdx.x >= EB) {
        int i = (blockIdx.x - EB) * 256 + threadIdx.x;
        if (i < N * 16) ((float4*)g_aggx)[i] = make_float4(0.f, 0.f, 0.f, 0.f);
        if (i < N) g_cnt[i] = 0;
        return;
    }
    __shared__ __align__(16) char sbuf[2][BUFSZ];
    int tid = threadIdx.x;
    int lane = tid & 31;
    int wid = tid >> 5;

    int j0 = 2 * lane;
    float wc0[16], wc1[16];
#pragma unroll
    for (int k = 0; k < 16; k++) {
        wc0[k] = w1[8192 + k * 64 + j0];
        wc1[k] = w1[8192 + k * 64 + j0 + 1];
    }
    float bb0 = b1[j0], bb1 = b1[j0 + 1];
    float ww0 = w2[j0], ww1 = w2[j0 + 1];
    float b2v = b2[0];

    int chunkBase = blockIdx.x * ECHUNK;
    int rem = E - chunkBase;
    if (rem <= 0) return;
    int nt = (rem < ECHUNK ? rem : ECHUNK);
    nt = (nt + ETILE - 1) / ETILE;

    const float4* ea4 = (const float4*)ea;

    auto stage = [&](int buf, int e0) {
        unsigned int sb = (unsigned int)__cvta_generic_to_shared(sbuf[buf]);
#pragma unroll
        for (int k = 0; k < 2; k++) {
            int t = tid * 2 + k;
            long gidx = (long)e0 * 4 + t;
            cp_async16(sb + t * 16, ea4 + gidx, gidx < (long)E * 4);
        }
        if (tid < 32) {
            int gi = e0 + tid * 4;
            cp_async16(sb + 8192 + tid * 16, ei + gi, gi < E);
        } else if (tid < 64) {
            int t = tid - 32;
            int gi = e0 + t * 4;
            cp_async16(sb + 8704 + t * 16, ei + E + gi, gi < E);
        }
    };

    stage(0, chunkBase);
    asm volatile("cp.async.commit_group;" ::: "memory");

    for (int t = 0; t < nt; t++) {
        if (t + 1 < nt) stage((t + 1) & 1, chunkBase + (t + 1) * ETILE);
        asm volatile("cp.async.commit_group;" ::: "memory");
        asm volatile("cp.async.wait_group 1;" ::: "memory");
        __syncthreads();

        const char* sb = sbuf[t & 1];
        const float4* eaS = (const float4*)sb;
        const int* srcS = (const int*)(sb + 8192);
        const int* dstS = (const int*)(sb + 8704);
        int eTile = chunkBase + t * ETILE;
        int rBase = wid * 16;
#pragma unroll 2
        for (int i = 0; i < 16; i += 2) {
            int r = rBase + i;
            int e = eTile + r;
            if (e >= E) break;
            int2 sAB = *(const int2*)(srcS + r);
            int2 dAB = *(const int2*)(dstS + r);
            __half2 avA = *(const __half2*)(g_A + (size_t)sAB.x * 64 + j0);
            __half2 bvA = *(const __half2*)(g_B + (size_t)dAB.x * 64 + j0);
            __half2 avB = *(const __half2*)(g_A + (size_t)sAB.y * 64 + j0);
            __half2 bvB = *(const __half2*)(g_B + (size_t)dAB.y * 64 + j0);
            float4 a0v = eaS[r * 4],     a1v = eaS[r * 4 + 1];
            float4 a2v = eaS[r * 4 + 2], a3v = eaS[r * 4 + 3];
            float4 c0v = eaS[r * 4 + 4], c1v = eaS[r * 4 + 5];
            float4 c2v = eaS[r * 4 + 6], c3v = eaS[r * 4 + 7];
            float2 fA = __half22float2(avA), gA = __half22float2(bvA);
            float2 fB = __half22float2(avB), gB = __half22float2(bvB);
            float h0A = fA.x + gA.x + bb0;
            float h1A = fA.y + gA.y + bb1;
            float h0B = fB.x + gB.x + bb0;
            float h1B = fB.y + gB.y + bb1;
            h0A += a0v.x * wc0[0]  + a0v.y * wc0[1]  + a0v.z * wc0[2]  + a0v.w * wc0[3]
                 + a1v.x * wc0[4]  + a1v.y * wc0[5]  + a1v.z * wc0[6]  + a1v.w * wc0[7]
                 + a2v.x * wc0[8]  + a2v.y * wc0[9]  + a2v.z * wc0[10] + a2v.w * wc0[11]
                 + a3v.x * wc0[12] + a3v.y * wc0[13] + a3v.z * wc0[14] + a3v.w * wc0[15];
            h1A += a0v.x * wc1[0]  + a0v.y * wc1[1]  + a0v.z * wc1[2]  + a0v.w * wc1[3]
                 + a1v.x * wc1[4]  + a1v.y * wc1[5]  + a1v.z * wc1[6]  + a1v.w * wc1[7]
                 + a2v.x * wc1[8]  + a2v.y * wc1[9]  + a2v.z * wc1[10] + a2v.w * wc1[11]
                 + a3v.x * wc1[12] + a3v.y * wc1[13] + a3v.z * wc1[14] + a3v.w * wc1[15];
            h0B += c0v.x * wc0[0]  + c0v.y * wc0[1]  + c0v.z * wc0[2]  + c0v.w * wc0[3]
                 + c1v.x * wc0[4]  + c1v.y * wc0[5]  + c1v.z * wc0[6]  + c1v.w * wc0[7]
                 + c2v.x * wc0[8]  + c2v.y * wc0[9]  + c2v.z * wc0[10] + c2v.w * wc0[11]
                 + c3v.x * wc0[12] + c3v.y * wc0[13] + c3v.z * wc0[14] + c3v.w * wc0[15];
            h1B += c0v.x * wc1[0]  + c0v.y * wc1[1]  + c0v.z * wc1[2]  + c0v.w * wc1[3]
                 + c1v.x * wc1[4]  + c1v.y * wc1[5]  + c1v.z * wc1[6]  + c1v.w * wc1[7]
                 + c2v.x * wc1[8]  + c2v.y * wc1[9]  + c2v.z * wc1[10] + c2v.w * wc1[11]
                 + c3v.x * wc1[12] + c3v.y * wc1[13] + c3v.z * wc1[14] + c3v.w * wc1[15];
            float pA = fmaxf(h0A, 0.f) * ww0 + fmaxf(h1A, 0.f) * ww1;
            float pB = fmaxf(h0B, 0.f) * ww0 + fmaxf(h1B, 0.f) * ww1;
#pragma unroll
            for (int off = 16; off; off >>= 1) {
                pA += __shfl_xor_sync(0xffffffffu, pA, off);
                pB += __shfl_xor_sync(0xffffffffu, pB, off);
            }
            if (lane == 0) {
                out[e] = pA + b2v;
                if (e + 1 < E) out[e + 1] = pB + b2v;
            }
        }
        __syncthreads();
    }
}

extern "C" void kernel_launch(void* const* d_in, const int* in_sizes, int n_in,
                              void* d_out, int out_size) {
    const float* xs = (const float*)d_in[0];
    const int* ei = (const int*)d_in[1];            // int32 (JAX x64 disabled)
    const float* ea = (const float*)d_in[2];
    const float* init_w = (const float*)d_in[3];
    const float* w_ih = (const float*)d_in[4];
    const float* w_hh = (const float*)d_in[5];
    const float* b_ih = (const float*)d_in[6];
    const float* b_hh = (const float*)d_in[7];
    const float* w1 = (const float*)d_in[8];
    const float* b1 = (const float*)d_in[9];
    const float* w2 = (const float*)d_in[10];
    const float* b2 = (const float*)d_in[11];
    float* out = (float*)d_out;

    int N = in_sizes[0] / (5 * 64);
    int E = in_sizes[1] / 2;

    // k1: LSTM
    lstm_kernel<<<64, 256>>>(init_w, w_ih, w_hh, b_ih, b_hh);
    // k2: in-degree histogram
    deg_count_kernel<<<(E + 255) / 256, 256>>>(ei, E);
    // k3: scatter raw X (edges + self loops)
    int items = E + N;
    scatter_x_kernel<<<(items * 16 + 255) / 256, 256>>>(xs + (size_t)4 * N * 64, ei, N, E);
    // k4: register-tiled triple GEMM (PROFILED slot #4)
    gemm_AB_kernel<<<(N + 63) / 64, 256>>>(w1, N);
    // k5: per-edge MLP + logit + tail zeroing
    int EB = (E + ECHUNK - 1) / ECHUNK;
    int ZB = (N * 16 + 255) / 256;
    edge_mlp_zero_kernel<<<EB + ZB, 256>>>(ei, ea, w1, b1, w2, b2, out, E, N, EB);
}

// round 15
// speedup vs baseline: 2.3194x; 1.1241x over previous
#include <cuda_runtime.h>
#include <cuda_fp16.h>
#include <cstdint>

// EvolvingGNN: T=5, N=100000, E=1600000, D=H=64, FE=16.
//  (1) Only xs_out[-1] is consumed -> one GCN pass with the LSTM weight after 5 steps.
//  (2) (P@X)@W == P@(X@W): aggregate raw X first, apply W after.
//  (3) Edge MLP factors: hid = relu(A[src] + B[dst] + ea@W1c + b1).
//  (4) Node pipeline has huge precision slack (measured: fp16 A/B -> rel_err 5e-7),
//      so the triple GEMM runs on tensor cores (m16n8k16 fp16 in / fp32 accum),
//      chaining Y through registers (C-fragment layout == A-fragment layout).
//  (5) Edge MLP: cp.async-staged ea/ei + fp16 A/B, register Wc, 2-edge ILP.
//  (6) Cross-call invariant: g_cnt/g_aggx zeroed by tail blocks of the last kernel.
//  Launch order: k1 lstm+deg (fused), k2 scatter, k3 gemm_mma, k4 edge_mlp (PROFILED).
// edge_index arrives as int32 (JAX x64-disabled downgrades jnp.int64).

#define NMAX 100000
#define ECHUNK 1024
#define ETILE 128
#define BUFSZ 9216

__device__ float  g_Wt[64 * 64];       // final evolved weight, [k][c]
__device__ int    g_cnt[NMAX];         // in-degree (excl self loop); zeroed by prev call
__device__ float  g_aggx[NMAX * 64];   // normAdj @ X; zeroed by prev call
__device__ __half g_A[NMAX * 64];      // fp16: relu(aggx@W) @ W1[0:64]
__device__ __half g_B[NMAX * 64];      // fp16: relu(aggx@W) @ W1[64:128]

__device__ __forceinline__ float sigmoidf(float x) { return 1.0f / (1.0f + expf(-x)); }

__device__ __forceinline__ void cp_async16(unsigned int smem, const void* gmem, bool pred) {
    asm volatile(
        "{\n\t.reg .pred p;\n\tsetp.ne.b32 p, %2, 0;\n\t"
        "@p cp.async.cg.shared.global [%0], [%1], 16;\n\t}"
        :: "r"(smem), "l"(gmem), "r"((int)pred) : "memory");
}

__device__ __forceinline__ void mma16816(float* c, const unsigned* a, const unsigned* b) {
    asm volatile(
        "mma.sync.aligned.m16n8k16.row.col.f32.f16.f16.f32 "
        "{%0,%1,%2,%3}, {%4,%5,%6,%7}, {%8,%9}, {%0,%1,%2,%3};"
        : "+f"(c[0]), "+f"(c[1]), "+f"(c[2]), "+f"(c[3])
        : "r"(a[0]), "r"(a[1]), "r"(a[2]), "r"(a[3]), "r"(b[0]), "r"(b[1]));
}

__device__ __forceinline__ unsigned packh2(float x, float y) {
    __half2 h = __floats2half2_rn(x, y);
    return *(unsigned*)&h;
}

// ---------------- k1: LSTM (blocks 0..63) + in-degree histogram (blocks 64..) ----------
__global__ void lstm_deg_kernel(const float* __restrict__ w0,
                                const float* __restrict__ w_ih,
                                const float* __restrict__ w_hh,
                                const float* __restrict__ b_ih,
                                const float* __restrict__ b_hh,
                                const int* __restrict__ ei, int E) {
    if (blockIdx.x >= 64) {
        int e = (blockIdx.x - 64) * 256 + threadIdx.x;
        if (e < E) atomicAdd(&g_cnt[ei[E + e]], 1);
        return;
    }
    __shared__ float xb[64], cr[64], gate[256];
    int r = blockIdx.x;
    int tid = threadIdx.x;
    if (tid < 64) {
        xb[tid] = w0[tid * 64 + r];
        cr[tid] = 0.f;
    }
    float bsum = b_ih[tid] + b_hh[tid];
    const float4* wi = (const float4*)(w_ih + tid * 64);
    const float4* wh = (const float4*)(w_hh + tid * 64);
    for (int t = 0; t < 5; t++) {
        __syncthreads();
        float acc = bsum;
#pragma unroll
        for (int k4 = 0; k4 < 16; k4++) {
            float4 a = wi[k4];
            float4 b = wh[k4];
            float x0 = xb[4 * k4], x1 = xb[4 * k4 + 1], x2 = xb[4 * k4 + 2], x3 = xb[4 * k4 + 3];
            acc += a.x * x0 + a.y * x1 + a.z * x2 + a.w * x3;
            if (t > 0)   // hidden state == previous output column for t>=1; 0 at t==0
                acc += b.x * x0 + b.y * x1 + b.z * x2 + b.w * x3;
        }
        gate[tid] = acc;
        __syncthreads();
        if (tid < 64) {
            float gi = sigmoidf(gate[tid]);
            float gf = sigmoidf(gate[64 + tid]);
            float gg = tanhf(gate[128 + tid]);
            float go = sigmoidf(gate[192 + tid]);
            float cn = gf * cr[tid] + gi * gg;
            float hn = go * tanhf(cn);
            cr[tid] = cn;
            xb[tid] = hn;
        }
    }
    if (tid < 64) g_Wt[tid * 64 + r] = xb[tid];
}

// ---------------- k2: scatter raw X: aggx[dst] += coef * x[src]; E edges + N self loops -
__global__ void scatter_x_kernel(const float* __restrict__ x,
                                 const int* __restrict__ ei, int N, int E) {
    int idx = blockIdx.x * 256 + threadIdx.x;
    int item = idx >> 4;
    int l = idx & 15;
    int lane = threadIdx.x & 31;
    int total = E + N;
    bool active = item < total;
    int src = 0, dst = 0;
    if (active) {
        if (item < E) { src = ei[item]; dst = ei[E + item]; }
        else          { src = dst = item - E; }
    }
    float c = 0.f;
    if ((lane & 15) == 0) {
        float ps = (float)(g_cnt[src] + 1);
        float pd = (float)(g_cnt[dst] + 1);
        c = rsqrtf(ps * pd);
    }
    c = __shfl_sync(0xffffffffu, c, lane & 16);
    if (active) {
        float4 v = *(const float4*)(x + (size_t)src * 64 + 4 * l);
        atomicAdd((float4*)(g_aggx + (size_t)dst * 64 + 4 * l),
                  make_float4(c * v.x, c * v.y, c * v.z, c * v.w));
    }
}

// ---------------- k3: tensor-core triple GEMM: Y=relu(X@W); A=Y@W1a; B=Y@W1b ------------
// Warp computes 16 rows. X loaded straight into A fragments (fp32->fp16 on the fly).
// Weights staged once in smem as fp16 TRANSPOSED (sW[c][k], pad 72) so each B fragment
// is two half2 LDS. Stage-1 C fragments relu+pack directly into stage-2 A fragments
// (identical lane mapping) -> no smem round trip for activations.
__global__ void __launch_bounds__(256) gemm_AB_mma_kernel(const float* __restrict__ w1, int n) {
    __shared__ __half sW[3][64][72];   // [0]=W, [1]=W1a, [2]=W1b ; sW[m][c][k] = Wm[k][c]
    int tid = threadIdx.x;
    for (int i = tid; i < 4096; i += 256) {
        int k = i >> 6, c = i & 63;
        sW[0][c][k] = __float2half(g_Wt[i]);
        sW[1][c][k] = __float2half(w1[i]);
        sW[2][c][k] = __float2half(w1[4096 + i]);
    }
    __syncthreads();

    int warp = tid >> 5, lane = tid & 31;
    int g = lane >> 2, tig = lane & 3;
    int row0 = blockIdx.x * 128 + warp * 16;
    int r0 = row0 + g, r1 = row0 + g + 8;
    bool v0 = r0 < n, v1 = r1 < n;

    // ---- load X as A fragments (4 k-tiles) ----
    unsigned a[4][4];
#pragma unroll
    for (int kt = 0; kt < 4; kt++) {
        int k0 = kt * 16 + 2 * tig;
        float2 x00 = v0 ? *(const float2*)(g_aggx + (size_t)r0 * 64 + k0)     : make_float2(0.f, 0.f);
        float2 x10 = v1 ? *(const float2*)(g_aggx + (size_t)r1 * 64 + k0)     : make_float2(0.f, 0.f);
        float2 x01 = v0 ? *(const float2*)(g_aggx + (size_t)r0 * 64 + k0 + 8) : make_float2(0.f, 0.f);
        float2 x11 = v1 ? *(const float2*)(g_aggx + (size_t)r1 * 64 + k0 + 8) : make_float2(0.f, 0.f);
        a[kt][0] = packh2(x00.x, x00.y);
        a[kt][1] = packh2(x10.x, x10.y);
        a[kt][2] = packh2(x01.x, x01.y);
        a[kt][3] = packh2(x11.x, x11.y);
    }

    float c[8][4];
    unsigned b[2];

    // ---- stage 1: Y = relu(X @ W) ----
#pragma unroll
    for (int nt = 0; nt < 8; nt++)
#pragma unroll
        for (int j = 0; j < 4; j++) c[nt][j] = 0.f;
#pragma unroll
    for (int nt = 0; nt < 8; nt++) {
#pragma unroll
        for (int kt = 0; kt < 4; kt++) {
            b[0] = *(const unsigned*)&sW[0][nt * 8 + g][kt * 16 + 2 * tig];
            b[1] = *(const unsigned*)&sW[0][nt * 8 + g][kt * 16 + 2 * tig + 8];
            mma16816(c[nt], a[kt], b);
        }
    }
    // relu + repack C -> Y A-fragments (same lane mapping)
    unsigned ya[4][4];
#pragma unroll
    for (int yt = 0; yt < 4; yt++) {
        ya[yt][0] = packh2(fmaxf(c[2 * yt][0], 0.f),     fmaxf(c[2 * yt][1], 0.f));
        ya[yt][1] = packh2(fmaxf(c[2 * yt][2], 0.f),     fmaxf(c[2 * yt][3], 0.f));
        ya[yt][2] = packh2(fmaxf(c[2 * yt + 1][0], 0.f), fmaxf(c[2 * yt + 1][1], 0.f));
        ya[yt][3] = packh2(fmaxf(c[2 * yt + 1][2], 0.f), fmaxf(c[2 * yt + 1][3], 0.f));
    }

    // ---- stage 2: A = Y @ W1a ----
#pragma unroll
    for (int nt = 0; nt < 8; nt++)
#pragma unroll
        for (int j = 0; j < 4; j++) c[nt][j] = 0.f;
#pragma unroll
    for (int nt = 0; nt < 8; nt++) {
#pragma unroll
        for (int kt = 0; kt < 4; kt++) {
            b[0] = *(const unsigned*)&sW[1][nt * 8 + g][kt * 16 + 2 * tig];
            b[1] = *(const unsigned*)&sW[1][nt * 8 + g][kt * 16 + 2 * tig + 8];
            mma16816(c[nt], ya[kt], b);
        }
    }
#pragma unroll
    for (int nt = 0; nt < 8; nt++) {
        int col = nt * 8 + 2 * tig;
        if (v0) *(unsigned*)(g_A + (size_t)r0 * 64 + col) = packh2(c[nt][0], c[nt][1]);
        if (v1) *(unsigned*)(g_A + (size_t)r1 * 64 + col) = packh2(c[nt][2], c[nt][3]);
    }

    // ---- stage 3: B = Y @ W1b ----
#pragma unroll
    for (int nt = 0; nt < 8; nt++)
#pragma unroll
        for (int j = 0; j < 4; j++) c[nt][j] = 0.f;
#pragma unroll
    for (int nt = 0; nt < 8; nt++) {
#pragma unroll
        for (int kt = 0; kt < 4; kt++) {
            b[0] = *(const unsigned*)&sW[2][nt * 8 + g][kt * 16 + 2 * tig];
            b[1] = *(const unsigned*)&sW[2][nt * 8 + g][kt * 16 + 2 * tig + 8];
            mma16816(c[nt], ya[kt], b);
        }
    }
#pragma unroll
    for (int nt = 0; nt < 8; nt++) {
        int col = nt * 8 + 2 * tig;
        if (v0) *(unsigned*)(g_B + (size_t)r0 * 64 + col) = packh2(c[nt][0], c[nt][1]);
        if (v1) *(unsigned*)(g_B + (size_t)r1 * 64 + col) = packh2(c[nt][2], c[nt][3]);
    }
}

// ---------------- k4 (PROFILED): Edge MLP, cp.async-staged ea/ei, fp16 A/B + zero tail --
__global__ void __launch_bounds__(256, 4)
edge_mlp_zero_kernel(const int* __restrict__ ei,
                     const float* __restrict__ ea,
                     const float* __restrict__ w1,
                     const float* __restrict__ b1,
                     const float* __restrict__ w2,
                     const float* __restrict__ b2,
                     float* __restrict__ out, int E, int N, int EB) {
    if (blockIdx.x >= EB) {
        int i = (blockIdx.x - EB) * 256 + threadIdx.x;
        if (i < N * 16) ((float4*)g_aggx)[i] = make_float4(0.f, 0.f, 0.f, 0.f);
        if (i < N) g_cnt[i] = 0;
        return;
    }
    __shared__ __align__(16) char sbuf[2][BUFSZ];
    int tid = threadIdx.x;
    int lane = tid & 31;
    int wid = tid >> 5;

    int j0 = 2 * lane;
    float wc0[16], wc1[16];
#pragma unroll
    for (int k = 0; k < 16; k++) {
        wc0[k] = w1[8192 + k * 64 + j0];
        wc1[k] = w1[8192 + k * 64 + j0 + 1];
    }
    float bb0 = b1[j0], bb1 = b1[j0 + 1];
    float ww0 = w2[j0], ww1 = w2[j0 + 1];
    float b2v = b2[0];

    int chunkBase = blockIdx.x * ECHUNK;
    int rem = E - chunkBase;
    if (rem <= 0) return;
    int nt = (rem < ECHUNK ? rem : ECHUNK);
    nt = (nt + ETILE - 1) / ETILE;

    const float4* ea4 = (const float4*)ea;

    auto stage = [&](int buf, int e0) {
        unsigned int sb = (unsigned int)__cvta_generic_to_shared(sbuf[buf]);
#pragma unroll
        for (int k = 0; k < 2; k++) {
            int t = tid * 2 + k;
            long gidx = (long)e0 * 4 + t;
            cp_async16(sb + t * 16, ea4 + gidx, gidx < (long)E * 4);
        }
        if (tid < 32) {
            int gi = e0 + tid * 4;
            cp_async16(sb + 8192 + tid * 16, ei + gi, gi < E);
        } else if (tid < 64) {
            int t = tid - 32;
            int gi = e0 + t * 4;
            cp_async16(sb + 8704 + t * 16, ei + E + gi, gi < E);
        }
    };

    stage(0, chunkBase);
    asm volatile("cp.async.commit_group;" ::: "memory");

    for (int t = 0; t < nt; t++) {
        if (t + 1 < nt) stage((t + 1) & 1, chunkBase + (t + 1) * ETILE);
        asm volatile("cp.async.commit_group;" ::: "memory");
        asm volatile("cp.async.wait_group 1;" ::: "memory");
        __syncthreads();

        const char* sb = sbuf[t & 1];
        const float4* eaS = (const float4*)sb;
        const int* srcS = (const int*)(sb + 8192);
        const int* dstS = (const int*)(sb + 8704);
        int eTile = chunkBase + t * ETILE;
        int rBase = wid * 16;
#pragma unroll 2
        for (int i = 0; i < 16; i += 2) {
            int r = rBase + i;
            int e = eTile + r;
            if (e >= E) break;
            int2 sAB = *(const int2*)(srcS + r);
            int2 dAB = *(const int2*)(dstS + r);
            __half2 avA = *(const __half2*)(g_A + (size_t)sAB.x * 64 + j0);
            __half2 bvA = *(const __half2*)(g_B + (size_t)dAB.x * 64 + j0);
            __half2 avB = *(const __half2*)(g_A + (size_t)sAB.y * 64 + j0);
            __half2 bvB = *(const __half2*)(g_B + (size_t)dAB.y * 64 + j0);
            float4 a0v = eaS[r * 4],     a1v = eaS[r * 4 + 1];
            float4 a2v = eaS[r * 4 + 2], a3v = eaS[r * 4 + 3];
            float4 c0v = eaS[r * 4 + 4], c1v = eaS[r * 4 + 5];
            float4 c2v = eaS[r * 4 + 6], c3v = eaS[r * 4 + 7];
            float2 fA = __half22float2(avA), gA = __half22float2(bvA);
            float2 fB = __half22float2(avB), gB = __half22float2(bvB);
            float h0A = fA.x + gA.x + bb0;
            float h1A = fA.y + gA.y + bb1;
            float h0B = fB.x + gB.x + bb0;
            float h1B = fB.y + gB.y + bb1;
            h0A += a0v.x * wc0[0]  + a0v.y * wc0[1]  + a0v.z * wc0[2]  + a0v.w * wc0[3]
                 + a1v.x * wc0[4]  + a1v.y * wc0[5]  + a1v.z * wc0[6]  + a1v.w * wc0[7]
                 + a2v.x * wc0[8]  + a2v.y * wc0[9]  + a2v.z * wc0[10] + a2v.w * wc0[11]
                 + a3v.x * wc0[12] + a3v.y * wc0[13] + a3v.z * wc0[14] + a3v.w * wc0[15];
            h1A += a0v.x * wc1[0]  + a0v.y * wc1[1]  + a0v.z * wc1[2]  + a0v.w * wc1[3]
                 + a1v.x * wc1[4]  + a1v.y * wc1[5]  + a1v.z * wc1[6]  + a1v.w * wc1[7]
                 + a2v.x * wc1[8]  + a2v.y * wc1[9]  + a2v.z * wc1[10] + a2v.w * wc1[11]
                 + a3v.x * wc1[12] + a3v.y * wc1[13] + a3v.z * wc1[14] + a3v.w * wc1[15];
            h0B += c0v.x * wc0[0]  + c0v.y * wc0[1]  + c0v.z * wc0[2]  + c0v.w * wc0[3]
                 + c1v.x * wc0[4]  + c1v.y * wc0[5]  + c1v.z * wc0[6]  + c1v.w * wc0[7]
                 + c2v.x * wc0[8]  + c2v.y * wc0[9]  + c2v.z * wc0[10] + c2v.w * wc0[11]
                 + c3v.x * wc0[12] + c3v.y * wc0[13] + c3v.z * wc0[14] + c3v.w * wc0[15];
            h1B += c0v.x * wc1[0]  + c0v.y * wc1[1]  + c0v.z * wc1[2]  + c0v.w * wc1[3]
                 + c1v.x * wc1[4]  + c1v.y * wc1[5]  + c1v.z * wc1[6]  + c1v.w * wc1[7]
                 + c2v.x * wc1[8]  + c2v.y * wc1[9]  + c2v.z * wc1[10] + c2v.w * wc1[11]
                 + c3v.x * wc1[12] + c3v.y * wc1[13] + c3v.z * wc1[14] + c3v.w * wc1[15];
            float pA = fmaxf(h0A, 0.f) * ww0 + fmaxf(h1A, 0.f) * ww1;
            float pB = fmaxf(h0B, 0.f) * ww0 + fmaxf(h1B, 0.f) * ww1;
#pragma unroll
            for (int off = 16; off; off >>= 1) {
                pA += __shfl_xor_sync(0xffffffffu, pA, off);
                pB += __shfl_xor_sync(0xffffffffu, pB, off);
            }
            if (lane == 0) {
                out[e] = pA + b2v;
                if (e + 1 < E) out[e + 1] = pB + b2v;
            }
        }
        __syncthreads();
    }
}

extern "C" void kernel_launch(void* const* d_in, const int* in_sizes, int n_in,
                              void* d_out, int out_size) {
    const float* xs = (const float*)d_in[0];
    const int* ei = (const int*)d_in[1];            // int32 (JAX x64 disabled)
    const float* ea = (const float*)d_in[2];
    const float* init_w = (const float*)d_in[3];
    const float* w_ih = (const float*)d_in[4];
    const float* w_hh = (const float*)d_in[5];
    const float* b_ih = (const float*)d_in[6];
    const float* b_hh = (const float*)d_in[7];
    const float* w1 = (const float*)d_in[8];
    const float* b1 = (const float*)d_in[9];
    const float* w2 = (const float*)d_in[10];
    const float* b2 = (const float*)d_in[11];
    float* out = (float*)d_out;

    int N = in_sizes[0] / (5 * 64);
    int E = in_sizes[1] / 2;

    // k1: LSTM + in-degree histogram (fused heterogeneous grid)
    lstm_deg_kernel<<<64 + (E + 255) / 256, 256>>>(init_w, w_ih, w_hh, b_ih, b_hh, ei, E);
    // k2: scatter raw X (edges + self loops)
    int items = E + N;
    scatter_x_kernel<<<(items * 16 + 255) / 256, 256>>>(xs + (size_t)4 * N * 64, ei, N, E);
    // k3: tensor-core triple GEMM (128 rows/block)
    gemm_AB_mma_kernel<<<(N + 127) / 128, 256>>>(w1, N);
    // k4: per-edge MLP + logit (PROFILED slot #4) + tail zeroing
    int EB = (E + ECHUNK - 1) / ECHUNK;
    int ZB = (N * 16 + 255) / 256;
    edge_mlp_zero_kernel<<<EB + ZB, 256>>>(ei, ea, w1, b1, w2, b2, out, E, N, EB);
}

// round 16
// speedup vs baseline: 2.5354x; 1.0931x over previous
#include <cuda_runtime.h>
#include <cuda_fp16.h>
#include <cstdint>

// EvolvingGNN: T=5, N=100000, E=1600000, D=H=64, FE=16.
//  (1) Only xs_out[-1] is consumed -> one GCN pass with the LSTM weight after 5 steps.
//  (2) (P@X)@W == P@(X@W): aggregate raw X first, apply W after.
//  (3) Edge MLP factors: hid = relu(A[src] + B[dst] + ea@W1c + b1).
//  (4) Node GEMMs on tensor cores (R15). NOW: ea@W1c also on tensor cores inside the
//      edge kernel (per 128-edge tile: warp does 8 mma.m16n8k16 instead of 512 FMA).
//  (5) Edge MLP: cp.async-staged ea/ei; epilogue in mma C-layout; quad shfl reduce.
//  (6) Cross-call invariant: g_cnt/g_aggx zeroed by tail blocks of the last kernel.
//  Launch order: k1 lstm+deg (fused), k2 scatter, k3 gemm_mma, k4 edge_mlp (PROFILED).
// edge_index arrives as int32 (JAX x64-disabled downgrades jnp.int64).

#define NMAX 100000
#define ECHUNK 1024
#define ETILE 128
#define BUFSZ 9216

__device__ float  g_Wt[64 * 64];       // final evolved weight, [k][c]
__device__ int    g_cnt[NMAX];         // in-degree (excl self loop); zeroed by prev call
__device__ float  g_aggx[NMAX * 64];   // normAdj @ X; zeroed by prev call
__device__ __half g_A[NMAX * 64];      // fp16: relu(aggx@W) @ W1[0:64]
__device__ __half g_B[NMAX * 64];      // fp16: relu(aggx@W) @ W1[64:128]

__device__ __forceinline__ float sigmoidf(float x) { return 1.0f / (1.0f + expf(-x)); }

__device__ __forceinline__ void cp_async16(unsigned int smem, const void* gmem, bool pred) {
    asm volatile(
        "{\n\t.reg .pred p;\n\tsetp.ne.b32 p, %2, 0;\n\t"
        "@p cp.async.cg.shared.global [%0], [%1], 16;\n\t}"
        :: "r"(smem), "l"(gmem), "r"((int)pred) : "memory");
}

__device__ __forceinline__ void mma16816(float* c, const unsigned* a, const unsigned* b) {
    asm volatile(
        "mma.sync.aligned.m16n8k16.row.col.f32.f16.f16.f32 "
        "{%0,%1,%2,%3}, {%4,%5,%6,%7}, {%8,%9}, {%0,%1,%2,%3};"
        : "+f"(c[0]), "+f"(c[1]), "+f"(c[2]), "+f"(c[3])
        : "r"(a[0]), "r"(a[1]), "r"(a[2]), "r"(a[3]), "r"(b[0]), "r"(b[1]));
}

__device__ __forceinline__ unsigned packh2(float x, float y) {
    __half2 h = __floats2half2_rn(x, y);
    return *(unsigned*)&h;
}

// ---------------- k1: LSTM (blocks 0..63) + in-degree histogram (blocks 64..) ----------
__global__ void lstm_deg_kernel(const float* __restrict__ w0,
                                const float* __restrict__ w_ih,
                                const float* __restrict__ w_hh,
                                const float* __restrict__ b_ih,
                                const float* __restrict__ b_hh,
                                const int* __restrict__ ei, int E) {
    if (blockIdx.x >= 64) {
        int e = (blockIdx.x - 64) * 256 + threadIdx.x;
        if (e < E) atomicAdd(&g_cnt[ei[E + e]], 1);
        return;
    }
    __shared__ float xb[64], cr[64], gate[256];
    int r = blockIdx.x;
    int tid = threadIdx.x;
    if (tid < 64) {
        xb[tid] = w0[tid * 64 + r];
        cr[tid] = 0.f;
    }
    float bsum = b_ih[tid] + b_hh[tid];
    const float4* wi = (const float4*)(w_ih + tid * 64);
    const float4* wh = (const float4*)(w_hh + tid * 64);
    for (int t = 0; t < 5; t++) {
        __syncthreads();
        float acc = bsum;
#pragma unroll
        for (int k4 = 0; k4 < 16; k4++) {
            float4 a = wi[k4];
            float4 b = wh[k4];
            float x0 = xb[4 * k4], x1 = xb[4 * k4 + 1], x2 = xb[4 * k4 + 2], x3 = xb[4 * k4 + 3];
            acc += a.x * x0 + a.y * x1 + a.z * x2 + a.w * x3;
            if (t > 0)
                acc += b.x * x0 + b.y * x1 + b.z * x2 + b.w * x3;
        }
        gate[tid] = acc;
        __syncthreads();
        if (tid < 64) {
            float gi = sigmoidf(gate[tid]);
            float gf = sigmoidf(gate[64 + tid]);
            float gg = tanhf(gate[128 + tid]);
            float go = sigmoidf(gate[192 + tid]);
            float cn = gf * cr[tid] + gi * gg;
            float hn = go * tanhf(cn);
            cr[tid] = cn;
            xb[tid] = hn;
        }
    }
    if (tid < 64) g_Wt[tid * 64 + r] = xb[tid];
}

// ---------------- k2: scatter raw X: aggx[dst] += coef * x[src]; E edges + N self loops -
__global__ void scatter_x_kernel(const float* __restrict__ x,
                                 const int* __restrict__ ei, int N, int E) {
    int idx = blockIdx.x * 256 + threadIdx.x;
    int item = idx >> 4;
    int l = idx & 15;
    int lane = threadIdx.x & 31;
    int total = E + N;
    bool active = item < total;
    int src = 0, dst = 0;
    if (active) {
        if (item < E) { src = ei[item]; dst = ei[E + item]; }
        else          { src = dst = item - E; }
    }
    float c = 0.f;
    if ((lane & 15) == 0) {
        float ps = (float)(g_cnt[src] + 1);
        float pd = (float)(g_cnt[dst] + 1);
        c = rsqrtf(ps * pd);
    }
    c = __shfl_sync(0xffffffffu, c, lane & 16);
    if (active) {
        float4 v = *(const float4*)(x + (size_t)src * 64 + 4 * l);
        atomicAdd((float4*)(g_aggx + (size_t)dst * 64 + 4 * l),
                  make_float4(c * v.x, c * v.y, c * v.z, c * v.w));
    }
}

// ---------------- k3: tensor-core triple GEMM: Y=relu(X@W); A=Y@W1a; B=Y@W1b ------------
__global__ void __launch_bounds__(256) gemm_AB_mma_kernel(const float* __restrict__ w1, int n) {
    __shared__ __half sW[3][64][72];
    int tid = threadIdx.x;
    for (int i = tid; i < 4096; i += 256) {
        int k = i >> 6, c = i & 63;
        sW[0][c][k] = __float2half(g_Wt[i]);
        sW[1][c][k] = __float2half(w1[i]);
        sW[2][c][k] = __float2half(w1[4096 + i]);
    }
    __syncthreads();

    int warp = tid >> 5, lane = tid & 31;
    int g = lane >> 2, tig = lane & 3;
    int row0 = blockIdx.x * 128 + warp * 16;
    int r0 = row0 + g, r1 = row0 + g + 8;
    bool v0 = r0 < n, v1 = r1 < n;

    unsigned a[4][4];
#pragma unroll
    for (int kt = 0; kt < 4; kt++) {
        int k0 = kt * 16 + 2 * tig;
        float2 x00 = v0 ? *(const float2*)(g_aggx + (size_t)r0 * 64 + k0)     : make_float2(0.f, 0.f);
        float2 x10 = v1 ? *(const float2*)(g_aggx + (size_t)r1 * 64 + k0)     : make_float2(0.f, 0.f);
        float2 x01 = v0 ? *(const float2*)(g_aggx + (size_t)r0 * 64 + k0 + 8) : make_float2(0.f, 0.f);
        float2 x11 = v1 ? *(const float2*)(g_aggx + (size_t)r1 * 64 + k0 + 8) : make_float2(0.f, 0.f);
        a[kt][0] = packh2(x00.x, x00.y);
        a[kt][1] = packh2(x10.x, x10.y);
        a[kt][2] = packh2(x01.x, x01.y);
        a[kt][3] = packh2(x11.x, x11.y);
    }

    float c[8][4];
    unsigned b[2];

#pragma unroll
    for (int nt = 0; nt < 8; nt++)
#pragma unroll
        for (int j = 0; j < 4; j++) c[nt][j] = 0.f;
#pragma unroll
    for (int nt = 0; nt < 8; nt++) {
#pragma unroll
        for (int kt = 0; kt < 4; kt++) {
            b[0] = *(const unsigned*)&sW[0][nt * 8 + g][kt * 16 + 2 * tig];
            b[1] = *(const unsigned*)&sW[0][nt * 8 + g][kt * 16 + 2 * tig + 8];
            mma16816(c[nt], a[kt], b);
        }
    }
    unsigned ya[4][4];
#pragma unroll
    for (int yt = 0; yt < 4; yt++) {
        ya[yt][0] = packh2(fmaxf(c[2 * yt][0], 0.f),     fmaxf(c[2 * yt][1], 0.f));
        ya[yt][1] = packh2(fmaxf(c[2 * yt][2], 0.f),     fmaxf(c[2 * yt][3], 0.f));
        ya[yt][2] = packh2(fmaxf(c[2 * yt + 1][0], 0.f), fmaxf(c[2 * yt + 1][1], 0.f));
        ya[yt][3] = packh2(fmaxf(c[2 * yt + 1][2], 0.f), fmaxf(c[2 * yt + 1][3], 0.f));
    }

#pragma unroll
    for (int nt = 0; nt < 8; nt++)
#pragma unroll
        for (int j = 0; j < 4; j++) c[nt][j] = 0.f;
#pragma unroll
    for (int nt = 0; nt < 8; nt++) {
#pragma unroll
        for (int kt = 0; kt < 4; kt++) {
            b[0] = *(const unsigned*)&sW[1][nt * 8 + g][kt * 16 + 2 * tig];
            b[1] = *(const unsigned*)&sW[1][nt * 8 + g][kt * 16 + 2 * tig + 8];
            mma16816(c[nt], ya[kt], b);
        }
    }
#pragma unroll
    for (int nt = 0; nt < 8; nt++) {
        int col = nt * 8 + 2 * tig;
        if (v0) *(unsigned*)(g_A + (size_t)r0 * 64 + col) = packh2(c[nt][0], c[nt][1]);
        if (v1) *(unsigned*)(g_A + (size_t)r1 * 64 + col) = packh2(c[nt][2], c[nt][3]);
    }

#pragma unroll
    for (int nt = 0; nt < 8; nt++)
#pragma unroll
        for (int j = 0; j < 4; j++) c[nt][j] = 0.f;
#pragma unroll
    for (int nt = 0; nt < 8; nt++) {
#pragma unroll
        for (int kt = 0; kt < 4; kt++) {
            b[0] = *(const unsigned*)&sW[2][nt * 8 + g][kt * 16 + 2 * tig];
            b[1] = *(const unsigned*)&sW[2][nt * 8 + g][kt * 16 + 2 * tig + 8];
            mma16816(c[nt], ya[kt], b);
        }
    }
#pragma unroll
    for (int nt = 0; nt < 8; nt++) {
        int col = nt * 8 + 2 * tig;
        if (v0) *(unsigned*)(g_B + (size_t)r0 * 64 + col) = packh2(c[nt][0], c[nt][1]);
        if (v1) *(unsigned*)(g_B + (size_t)r1 * 64 + col) = packh2(c[nt][2], c[nt][3]);
    }
}

// ---------------- k4 (PROFILED): Edge MLP via tensor cores -------------------------------
// Per 128-edge tile: warp owns 16 edges, computes ea@W1c with 8 mma.m16n8k16
// (A frags from staged fp32 ea, B frags = W1c register-hoisted). Epilogue adds
// gathered fp16 A[src]/B[dst] + b1 in the C layout, relu, dots w2, quad-reduces
// over tig (shfl_xor 1,2); lanes tig==0 store rows g and g+8.
__global__ void __launch_bounds__(256)
edge_mlp_zero_kernel(const int* __restrict__ ei,
                     const float* __restrict__ ea,
                     const float* __restrict__ w1,
                     const float* __restrict__ b1,
                     const float* __restrict__ w2,
                     const float* __restrict__ b2,
                     float* __restrict__ out, int E, int N, int EB) {
    if (blockIdx.x >= EB) {
        int i = (blockIdx.x - EB) * 256 + threadIdx.x;
        if (i < N * 16) ((float4*)g_aggx)[i] = make_float4(0.f, 0.f, 0.f, 0.f);
        if (i < N) g_cnt[i] = 0;
        return;
    }
    __shared__ __align__(16) char sbuf[2][BUFSZ];
    int tid = threadIdx.x;
    int lane = tid & 31;
    int wid = tid >> 5;
    int g = lane >> 2, tig = lane & 3;

    // B fragments of W1c (k=16, col-major frags), constant across tiles.
    // b0 = {W1c[2tig][col], W1c[2tig+1][col]}, b1f = {W1c[2tig+8][col], W1c[2tig+9][col]},
    // col = nt*8+g. W1c[k][c] = w1[8192 + k*64 + c].
    unsigned bf0[8], bf1[8];
    float w2c0[8], w2c1[8], b1c0[8], b1c1[8];
#pragma unroll
    for (int nt = 0; nt < 8; nt++) {
        int col = nt * 8 + g;
        bf0[nt] = packh2(w1[8192 + (2 * tig) * 64 + col],     w1[8192 + (2 * tig + 1) * 64 + col]);
        bf1[nt] = packh2(w1[8192 + (2 * tig + 8) * 64 + col], w1[8192 + (2 * tig + 9) * 64 + col]);
        int c0 = nt * 8 + 2 * tig;
        w2c0[nt] = w2[c0];     w2c1[nt] = w2[c0 + 1];
        b1c0[nt] = b1[c0];     b1c1[nt] = b1[c0 + 1];
    }
    float b2v = b2[0];

    int chunkBase = blockIdx.x * ECHUNK;
    int rem = E - chunkBase;
    if (rem <= 0) return;
    int nt_tiles = (rem < ECHUNK ? rem : ECHUNK);
    nt_tiles = (nt_tiles + ETILE - 1) / ETILE;

    const float4* ea4 = (const float4*)ea;

    auto stage = [&](int buf, int e0) {
        unsigned int sb = (unsigned int)__cvta_generic_to_shared(sbuf[buf]);
#pragma unroll
        for (int k = 0; k < 2; k++) {
            int t = tid * 2 + k;
            long gidx = (long)e0 * 4 + t;
            cp_async16(sb + t * 16, ea4 + gidx, gidx < (long)E * 4);
        }
        if (tid < 32) {
            int gi = e0 + tid * 4;
            cp_async16(sb + 8192 + tid * 16, ei + gi, gi < E);
        } else if (tid < 64) {
            int t = tid - 32;
            int gi = e0 + t * 4;
            cp_async16(sb + 8704 + t * 16, ei + E + gi, gi < E);
        }
    };

    stage(0, chunkBase);
    asm volatile("cp.async.commit_group;" ::: "memory");

    for (int t = 0; t < nt_tiles; t++) {
        if (t + 1 < nt_tiles) stage((t + 1) & 1, chunkBase + (t + 1) * ETILE);
        asm volatile("cp.async.commit_group;" ::: "memory");
        asm volatile("cp.async.wait_group 1;" ::: "memory");
        __syncthreads();

        const char* sb = sbuf[t & 1];
        const float2* eaS2 = (const float2*)sb;       // ea tile as float2 (8 per edge)
        const int* srcS = (const int*)(sb + 8192);
        const int* dstS = (const int*)(sb + 8704);
        int eTile = chunkBase + t * ETILE;
        int rBase = wid * 16;                          // warp's 16 edges within tile

        int e0 = eTile + rBase + g;                    // row g
        int e1 = e0 + 8;                               // row g+8
        bool v0 = e0 < E, v1 = e1 < E;
        int src0 = 0, dst0 = 0, src1 = 0, dst1 = 0;
        if (v0) { src0 = srcS[rBase + g];     dst0 = dstS[rBase + g]; }
        if (v1) { src1 = srcS[rBase + g + 8]; dst1 = dstS[rBase + g + 8]; }

        // A fragments from staged fp32 ea: rows (g, g+8), k cols (2tig.., 2tig+8..)
        unsigned a[4];
        {
            float2 x00 = eaS2[(rBase + g) * 8 + tig];
            float2 x10 = eaS2[(rBase + g + 8) * 8 + tig];
            float2 x01 = eaS2[(rBase + g) * 8 + tig + 4];
            float2 x11 = eaS2[(rBase + g + 8) * 8 + tig + 4];
            a[0] = packh2(x00.x, x00.y);
            a[1] = packh2(x10.x, x10.y);
            a[2] = packh2(x01.x, x01.y);
            a[3] = packh2(x11.x, x11.y);
        }

        // c[nt][0,1] = row g cols nt*8+2tig,+1 ; c[nt][2,3] = row g+8 same cols
        float c[8][4];
#pragma unroll
        for (int nt = 0; nt < 8; nt++) {
            c[nt][0] = c[nt][1] = c[nt][2] = c[nt][3] = 0.f;
            unsigned bb[2] = { bf0[nt], bf1[nt] };
            mma16816(c[nt], a, bb);
        }

        // epilogue: + A[src]+B[dst]+b1, relu, dot w2 (per-lane partial over its 16 cols)
        float pA = 0.f, pB = 0.f;
#pragma unroll
        for (int nt = 0; nt < 8; nt++) {
            int c0 = nt * 8 + 2 * tig;
            float2 aS0 = v0 ? __half22float2(*(const __half2*)(g_A + (size_t)src0 * 64 + c0))
                            : make_float2(0.f, 0.f);
            float2 bD0 = v0 ? __half22float2(*(const __half2*)(g_B + (size_t)dst0 * 64 + c0))
                            : make_float2(0.f, 0.f);
            float2 aS1 = v1 ? __half22float2(*(const __half2*)(g_A + (size_t)src1 * 64 + c0))
                            : make_float2(0.f, 0.f);
            float2 bD1 = v1 ? __half22float2(*(const __half2*)(g_B + (size_t)dst1 * 64 + c0))
                            : make_float2(0.f, 0.f);
            float h00 = c[nt][0] + aS0.x + bD0.x + b1c0[nt];
            float h01 = c[nt][1] + aS0.y + bD0.y + b1c1[nt];
            float h10 = c[nt][2] + aS1.x + bD1.x + b1c0[nt];
            float h11 = c[nt][3] + aS1.y + bD1.y + b1c1[nt];
            pA += fmaxf(h00, 0.f) * w2c0[nt] + fmaxf(h01, 0.f) * w2c1[nt];
            pB += fmaxf(h10, 0.f) * w2c0[nt] + fmaxf(h11, 0.f) * w2c1[nt];
        }
        // reduce over tig (lane bits 0-1)
        pA += __shfl_xor_sync(0xffffffffu, pA, 1);
        pA += __shfl_xor_sync(0xffffffffu, pA, 2);
        pB += __shfl_xor_sync(0xffffffffu, pB, 1);
        pB += __shfl_xor_sync(0xffffffffu, pB, 2);
        if (tig == 0) {
            if (v0) out[e0] = pA + b2v;
            if (v1) out[e1] = pB + b2v;
        }
        __syncthreads();
    }
}

extern "C" void kernel_launch(void* const* d_in, const int* in_sizes, int n_in,
                              void* d_out, int out_size) {
    const float* xs = (const float*)d_in[0];
    const int* ei = (const int*)d_in[1];            // int32 (JAX x64 disabled)
    const float* ea = (const float*)d_in[2];
    const float* init_w = (const float*)d_in[3];
    const float* w_ih = (const float*)d_in[4];
    const float* w_hh = (const float*)d_in[5];
    const float* b_ih = (const float*)d_in[6];
    const float* b_hh = (const float*)d_in[7];
    const float* w1 = (const float*)d_in[8];
    const float* b1 = (const float*)d_in[9];
    const float* w2 = (const float*)d_in[10];
    const float* b2 = (const float*)d_in[11];
    float* out = (float*)d_out;

    int N = in_sizes[0] / (5 * 64);
    int E = in_sizes[1] / 2;

    // k1: LSTM + in-degree histogram (fused heterogeneous grid)
    lstm_deg_kernel<<<64 + (E + 255) / 256, 256>>>(init_w, w_ih, w_hh, b_ih, b_hh, ei, E);
    // k2: scatter raw X (edges + self loops)
    int items = E + N;
    scatter_x_kernel<<<(items * 16 + 255) / 256, 256>>>(xs + (size_t)4 * N * 64, ei, N, E);
    // k3: tensor-core triple GEMM (128 rows/block)
    gemm_AB_mma_kernel<<<(N + 127) / 128, 256>>>(w1, N);
    // k4: per-edge MLP via tensor cores (PROFILED slot #4) + tail zeroing
    int EB = (E + ECHUNK - 1) / ECHUNK;
    int ZB = (N * 16 + 255) / 256;
    edge_mlp_zero_kernel<<<EB + ZB, 256>>>(ei, ea, w1, b1, w2, b2, out, E, N, EB);
}

// round 17
// speedup vs baseline: 3.1680x; 1.2495x over previous
#include <cuda_runtime.h>
#include <cuda_fp16.h>
#include <cstdint>

// EvolvingGNN: T=5, N=100000, E=1600000, D=H=64, FE=16.
//  (1) Only xs_out[-1] is consumed -> one GCN pass with the LSTM weight after 5 steps.
//  (2) (P@X)@W == P@(X@W): aggregate raw X first, apply W after.
//  (3) Edge MLP factors: hid = relu(A[src] + B[dst] + ea@W1c + b1).
//  (4) All GEMM work on tensor cores (m16n8k16, fp16 in / fp32 accum).
//  (5) Scatter: fp16 payload + v4.f16x2 vector reductions (halved L2 traffic).
//  (6) Edge MLP: cp.async-staged ea/ei; Wc/b1/w2 constants in smem (regs<64 -> occ 4/SM).
//  (7) Cross-call invariant: g_cnt/g_aggx zeroed by tail blocks of the last kernel.
//  Launch order: k1 lstm+deg+convert, k2 scatter, k3 gemm_mma, k4 edge_mlp (PROFILED).
// edge_index arrives as int32 (JAX x64-disabled downgrades jnp.int64).

#define NMAX 100000
#define ECHUNK 1024
#define ETILE 128
#define BUFSZ 9216

__device__ float  g_Wt[64 * 64];       // final evolved weight, [k][c]
__device__ int    g_cnt[NMAX];         // in-degree (excl self loop); zeroed by prev call
__device__ __half g_xh[NMAX * 64];     // fp16 copy of xs[4]
__device__ __half g_aggx[NMAX * 64];   // fp16 normAdj @ X; zeroed by prev call
__device__ __half g_A[NMAX * 64];      // fp16: relu(aggx@W) @ W1[0:64]
__device__ __half g_B[NMAX * 64];      // fp16: relu(aggx@W) @ W1[64:128]

__device__ __forceinline__ float sigmoidf(float x) { return 1.0f / (1.0f + expf(-x)); }

__device__ __forceinline__ void cp_async16(unsigned int smem, const void* gmem, bool pred) {
    asm volatile(
        "{\n\t.reg .pred p;\n\tsetp.ne.b32 p, %2, 0;\n\t"
        "@p cp.async.cg.shared.global [%0], [%1], 16;\n\t}"
        :: "r"(smem), "l"(gmem), "r"((int)pred) : "memory");
}

__device__ __forceinline__ void mma16816(float* c, const unsigned* a, const unsigned* b) {
    asm volatile(
        "mma.sync.aligned.m16n8k16.row.col.f32.f16.f16.f32 "
        "{%0,%1,%2,%3}, {%4,%5,%6,%7}, {%8,%9}, {%0,%1,%2,%3};"
        : "+f"(c[0]), "+f"(c[1]), "+f"(c[2]), "+f"(c[3])
        : "r"(a[0]), "r"(a[1]), "r"(a[2]), "r"(a[3]), "r"(b[0]), "r"(b[1]));
}

__device__ __forceinline__ unsigned packh2(float x, float y) {
    __half2 h = __floats2half2_rn(x, y);
    return *(unsigned*)&h;
}

// ---------------- k1: LSTM (blocks 0..63) + deg histogram + x->fp16 convert -------------
__global__ void lstm_deg_cvt_kernel(const float* __restrict__ w0,
                                    const float* __restrict__ w_ih,
                                    const float* __restrict__ w_hh,
                                    const float* __restrict__ b_ih,
                                    const float* __restrict__ b_hh,
                                    const int* __restrict__ ei,
                                    const float* __restrict__ x,
                                    int N, int E, int DEGB) {
    if (blockIdx.x >= 64u + DEGB) {
        // convert region: thread j converts 8 floats -> 8 halves
        int j = (blockIdx.x - 64 - DEGB) * 256 + threadIdx.x;
        if (j * 8 < N * 64) {
            const float4* x4 = (const float4*)x;
            float4 f0 = x4[j * 2], f1 = x4[j * 2 + 1];
            uint4 o;
            o.x = packh2(f0.x, f0.y);
            o.y = packh2(f0.z, f0.w);
            o.z = packh2(f1.x, f1.y);
            o.w = packh2(f1.z, f1.w);
            ((uint4*)g_xh)[j] = o;
        }
        return;
    }
    if (blockIdx.x >= 64) {
        int e = (blockIdx.x - 64) * 256 + threadIdx.x;
        if (e < E) atomicAdd(&g_cnt[ei[E + e]], 1);
        return;
    }
    __shared__ float xb[64], cr[64], gate[256];
    int r = blockIdx.x;
    int tid = threadIdx.x;
    if (tid < 64) {
        xb[tid] = w0[tid * 64 + r];
        cr[tid] = 0.f;
    }
    float bsum = b_ih[tid] + b_hh[tid];
    const float4* wi = (const float4*)(w_ih + tid * 64);
    const float4* wh = (const float4*)(w_hh + tid * 64);
    for (int t = 0; t < 5; t++) {
        __syncthreads();
        float acc = bsum;
#pragma unroll
        for (int k4 = 0; k4 < 16; k4++) {
            float4 a = wi[k4];
            float4 b = wh[k4];
            float x0 = xb[4 * k4], x1 = xb[4 * k4 + 1], x2 = xb[4 * k4 + 2], x3 = xb[4 * k4 + 3];
            acc += a.x * x0 + a.y * x1 + a.z * x2 + a.w * x3;
            if (t > 0)
                acc += b.x * x0 + b.y * x1 + b.z * x2 + b.w * x3;
        }
        gate[tid] = acc;
        __syncthreads();
        if (tid < 64) {
            float gi = sigmoidf(gate[tid]);
            float gf = sigmoidf(gate[64 + tid]);
            float gg = tanhf(gate[128 + tid]);
            float go = sigmoidf(gate[192 + tid]);
            float cn = gf * cr[tid] + gi * gg;
            float hn = go * tanhf(cn);
            cr[tid] = cn;
            xb[tid] = hn;
        }
    }
    if (tid < 64) g_Wt[tid * 64 + r] = xb[tid];
}

// ---------------- k2: fp16 scatter: aggx[dst] += coef * xh[src]; E edges + N self loops -
// 8 lanes per item; each lane handles 8 halves (16 B) via v4.f16x2 vector reduction.
__global__ void scatter_xh_kernel(const int* __restrict__ ei, int N, int E) {
    int idx = blockIdx.x * 256 + threadIdx.x;
    int item = idx >> 3;
    int l = idx & 7;
    int lane = threadIdx.x & 31;
    int total = E + N;
    bool active = item < total;
    int src = 0, dst = 0;
    if (active) {
        if (item < E) { src = ei[item]; dst = ei[E + item]; }
        else          { src = dst = item - E; }
    }
    float c = 0.f;
    if ((lane & 7) == 0 && active) {
        float ps = (float)(g_cnt[src] + 1);
        float pd = (float)(g_cnt[dst] + 1);
        c = rsqrtf(ps * pd);
    }
    c = __shfl_sync(0xffffffffu, c, lane & 24);
    if (active) {
        __half2 c2 = __float2half2_rn(c);
        uint4 v = ((const uint4*)(g_xh + (size_t)src * 64))[l];
        __half2 m0 = __hmul2(*(__half2*)&v.x, c2);
        __half2 m1 = __hmul2(*(__half2*)&v.y, c2);
        __half2 m2 = __hmul2(*(__half2*)&v.z, c2);
        __half2 m3 = __hmul2(*(__half2*)&v.w, c2);
        __half* p = g_aggx + (size_t)dst * 64 + l * 8;
        asm volatile(
            "red.global.add.noftz.v4.f16x2 [%0], {%1,%2,%3,%4};"
            :: "l"(p), "r"(*(unsigned*)&m0), "r"(*(unsigned*)&m1),
               "r"(*(unsigned*)&m2), "r"(*(unsigned*)&m3) : "memory");
    }
}

// ---------------- k3: tensor-core triple GEMM: Y=relu(X@W); A=Y@W1a; B=Y@W1b ------------
__global__ void __launch_bounds__(256) gemm_AB_mma_kernel(const float* __restrict__ w1, int n) {
    __shared__ __half sW[3][64][72];
    int tid = threadIdx.x;
    for (int i = tid; i < 4096; i += 256) {
        int k = i >> 6, c = i & 63;
        sW[0][c][k] = __float2half(g_Wt[i]);
        sW[1][c][k] = __float2half(w1[i]);
        sW[2][c][k] = __float2half(w1[4096 + i]);
    }
    __syncthreads();

    int warp = tid >> 5, lane = tid & 31;
    int g = lane >> 2, tig = lane & 3;
    int row0 = blockIdx.x * 128 + warp * 16;
    int r0 = row0 + g, r1 = row0 + g + 8;
    bool v0 = r0 < n, v1 = r1 < n;

    // aggx is fp16: A fragments load directly as half2
    unsigned a[4][4];
#pragma unroll
    for (int kt = 0; kt < 4; kt++) {
        int k0 = kt * 16 + 2 * tig;
        a[kt][0] = v0 ? *(const unsigned*)(g_aggx + (size_t)r0 * 64 + k0)     : 0u;
        a[kt][1] = v1 ? *(const unsigned*)(g_aggx + (size_t)r1 * 64 + k0)     : 0u;
        a[kt][2] = v0 ? *(const unsigned*)(g_aggx + (size_t)r0 * 64 + k0 + 8) : 0u;
        a[kt][3] = v1 ? *(const unsigned*)(g_aggx + (size_t)r1 * 64 + k0 + 8) : 0u;
    }

    float c[8][4];
    unsigned b[2];

#pragma unroll
    for (int nt = 0; nt < 8; nt++)
#pragma unroll
        for (int j = 0; j < 4; j++) c[nt][j] = 0.f;
#pragma unroll
    for (int nt = 0; nt < 8; nt++) {
#pragma unroll
        for (int kt = 0; kt < 4; kt++) {
            b[0] = *(const unsigned*)&sW[0][nt * 8 + g][kt * 16 + 2 * tig];
            b[1] = *(const unsigned*)&sW[0][nt * 8 + g][kt * 16 + 2 * tig + 8];
            mma16816(c[nt], a[kt], b);
        }
    }
    unsigned ya[4][4];
#pragma unroll
    for (int yt = 0; yt < 4; yt++) {
        ya[yt][0] = packh2(fmaxf(c[2 * yt][0], 0.f),     fmaxf(c[2 * yt][1], 0.f));
        ya[yt][1] = packh2(fmaxf(c[2 * yt][2], 0.f),     fmaxf(c[2 * yt][3], 0.f));
        ya[yt][2] = packh2(fmaxf(c[2 * yt + 1][0], 0.f), fmaxf(c[2 * yt + 1][1], 0.f));
        ya[yt][3] = packh2(fmaxf(c[2 * yt + 1][2], 0.f), fmaxf(c[2 * yt + 1][3], 0.f));
    }

#pragma unroll
    for (int nt = 0; nt < 8; nt++)
#pragma unroll
        for (int j = 0; j < 4; j++) c[nt][j] = 0.f;
#pragma unroll
    for (int nt = 0; nt < 8; nt++) {
#pragma unroll
        for (int kt = 0; kt < 4; kt++) {
            b[0] = *(const unsigned*)&sW[1][nt * 8 + g][kt * 16 + 2 * tig];
            b[1] = *(const unsigned*)&sW[1][nt * 8 + g][kt * 16 + 2 * tig + 8];
            mma16816(c[nt], ya[kt], b);
        }
    }
#pragma unroll
    for (int nt = 0; nt < 8; nt++) {
        int col = nt * 8 + 2 * tig;
        if (v0) *(unsigned*)(g_A + (size_t)r0 * 64 + col) = packh2(c[nt][0], c[nt][1]);
        if (v1) *(unsigned*)(g_A + (size_t)r1 * 64 + col) = packh2(c[nt][2], c[nt][3]);
    }

#pragma unroll
    for (int nt = 0; nt < 8; nt++)
#pragma unroll
        for (int j = 0; j < 4; j++) c[nt][j] = 0.f;
#pragma unroll
    for (int nt = 0; nt < 8; nt++) {
#pragma unroll
        for (int kt = 0; kt < 4; kt++) {
            b[0] = *(const unsigned*)&sW[2][nt * 8 + g][kt * 16 + 2 * tig];
            b[1] = *(const unsigned*)&sW[2][nt * 8 + g][kt * 16 + 2 * tig + 8];
            mma16816(c[nt], ya[kt], b);
        }
    }
#pragma unroll
    for (int nt = 0; nt < 8; nt++) {
        int col = nt * 8 + 2 * tig;
        if (v0) *(unsigned*)(g_B + (size_t)r0 * 64 + col) = packh2(c[nt][0], c[nt][1]);
        if (v1) *(unsigned*)(g_B + (size_t)r1 * 64 + col) = packh2(c[nt][2], c[nt][3]);
    }
}

// ---------------- k4 (PROFILED): Edge MLP via tensor cores, smem constants --------------
// Per 128-edge tile: warp owns 16 edges, 8 mma.m16n8k16 for ea@W1c. Constants (W1c B-frags,
// b1, w2) live in smem indexed [nt*32+lane] -> regs < 64 -> 4 blocks/SM.
__global__ void __launch_bounds__(256, 4)
edge_mlp_zero_kernel(const int* __restrict__ ei,
                     const float* __restrict__ ea,
                     const float* __restrict__ w1,
                     const float* __restrict__ b1,
                     const float* __restrict__ w2,
                     const float* __restrict__ b2,
                     float* __restrict__ out, int E, int N, int EB) {
    if (blockIdx.x >= EB) {
        int i = (blockIdx.x - EB) * 256 + threadIdx.x;
        if (i < N * 8) ((uint4*)g_aggx)[i] = make_uint4(0u, 0u, 0u, 0u);
        if (i < N) g_cnt[i] = 0;
        return;
    }
    __shared__ __align__(16) char sbuf[2][BUFSZ];
    __shared__ unsigned sBf0[256], sBf1[256];
    __shared__ float sW2a[256], sW2b[256], sB1a[256], sB1b[256];
    int tid = threadIdx.x;
    int lane = tid & 31;
    int wid = tid >> 5;
    int g = lane >> 2, tig = lane & 3;

    {   // per-lane-class constants -> smem [nt*32 + lane]
        int nt = tid >> 5, lc = tid & 31;
        int gg = lc >> 2, tt = lc & 3;
        int col = nt * 8 + gg;
        sBf0[tid] = packh2(w1[8192 + (2 * tt) * 64 + col],     w1[8192 + (2 * tt + 1) * 64 + col]);
        sBf1[tid] = packh2(w1[8192 + (2 * tt + 8) * 64 + col], w1[8192 + (2 * tt + 9) * 64 + col]);
        int c0 = nt * 8 + 2 * tt;
        sW2a[tid] = w2[c0];  sW2b[tid] = w2[c0 + 1];
        sB1a[tid] = b1[c0];  sB1b[tid] = b1[c0 + 1];
    }
    float b2v = b2[0];

    int chunkBase = blockIdx.x * ECHUNK;
    int rem = E - chunkBase;
    if (rem <= 0) return;
    int nt_tiles = (rem < ECHUNK ? rem : ECHUNK);
    nt_tiles = (nt_tiles + ETILE - 1) / ETILE;

    const float4* ea4 = (const float4*)ea;

    auto stage = [&](int buf, int e0) {
        unsigned int sb = (unsigned int)__cvta_generic_to_shared(sbuf[buf]);
#pragma unroll
        for (int k = 0; k < 2; k++) {
            int t = tid * 2 + k;
            long gidx = (long)e0 * 4 + t;
            cp_async16(sb + t * 16, ea4 + gidx, gidx < (long)E * 4);
        }
        if (tid < 32) {
            int gi = e0 + tid * 4;
            cp_async16(sb + 8192 + tid * 16, ei + gi, gi < E);
        } else if (tid < 64) {
            int t = tid - 32;
            int gi = e0 + t * 4;
            cp_async16(sb + 8704 + t * 16, ei + E + gi, gi < E);
        }
    };

    stage(0, chunkBase);
    asm volatile("cp.async.commit_group;" ::: "memory");
    __syncthreads();   // constants visible

    for (int t = 0; t < nt_tiles; t++) {
        if (t + 1 < nt_tiles) stage((t + 1) & 1, chunkBase + (t + 1) * ETILE);
        asm volatile("cp.async.commit_group;" ::: "memory");
        asm volatile("cp.async.wait_group 1;" ::: "memory");
        __syncthreads();

        const char* sb = sbuf[t & 1];
        const float2* eaS2 = (const float2*)sb;
        const int* srcS = (const int*)(sb + 8192);
        const int* dstS = (const int*)(sb + 8704);
        int eTile = chunkBase + t * ETILE;
        int rBase = wid * 16;

        int e0 = eTile + rBase + g;
        int e1 = e0 + 8;
        bool v0 = e0 < E, v1 = e1 < E;
        int src0 = 0, dst0 = 0, src1 = 0, dst1 = 0;
        if (v0) { src0 = srcS[rBase + g];     dst0 = dstS[rBase + g]; }
        if (v1) { src1 = srcS[rBase + g + 8]; dst1 = dstS[rBase + g + 8]; }

        unsigned a[4];
        {
            float2 x00 = eaS2[(rBase + g) * 8 + tig];
            float2 x10 = eaS2[(rBase + g + 8) * 8 + tig];
            float2 x01 = eaS2[(rBase + g) * 8 + tig + 4];
            float2 x11 = eaS2[(rBase + g + 8) * 8 + tig + 4];
            a[0] = packh2(x00.x, x00.y);
            a[1] = packh2(x10.x, x10.y);
            a[2] = packh2(x01.x, x01.y);
            a[3] = packh2(x11.x, x11.y);
        }

        float c[8][4];
#pragma unroll
        for (int nt = 0; nt < 8; nt++) {
            c[nt][0] = c[nt][1] = c[nt][2] = c[nt][3] = 0.f;
            unsigned bb[2] = { sBf0[nt * 32 + lane], sBf1[nt * 32 + lane] };
            mma16816(c[nt], a, bb);
        }

        float pA = 0.f, pB = 0.f;
#pragma unroll
        for (int nt = 0; nt < 8; nt++) {
            int c0 = nt * 8 + 2 * tig;
            int ci = nt * 32 + lane;
            float2 aS0 = v0 ? __half22float2(*(const __half2*)(g_A + (size_t)src0 * 64 + c0))
                            : make_float2(0.f, 0.f);
            float2 bD0 = v0 ? __half22float2(*(const __half2*)(g_B + (size_t)dst0 * 64 + c0))
                            : make_float2(0.f, 0.f);
            float2 aS1 = v1 ? __half22float2(*(const __half2*)(g_A + (size_t)src1 * 64 + c0))
                            : make_float2(0.f, 0.f);
            float2 bD1 = v1 ? __half22float2(*(const __half2*)(g_B + (size_t)dst1 * 64 + c0))
                            : make_float2(0.f, 0.f);
            float b1a = sB1a[ci], b1b = sB1b[ci];
            float w2a = sW2a[ci], w2b = sW2b[ci];
            float h00 = c[nt][0] + aS0.x + bD0.x + b1a;
            float h01 = c[nt][1] + aS0.y + bD0.y + b1b;
            float h10 = c[nt][2] + aS1.x + bD1.x + b1a;
            float h11 = c[nt][3] + aS1.y + bD1.y + b1b;
            pA += fmaxf(h00, 0.f) * w2a + fmaxf(h01, 0.f) * w2b;
            pB += fmaxf(h10, 0.f) * w2a + fmaxf(h11, 0.f) * w2b;
        }
        pA += __shfl_xor_sync(0xffffffffu, pA, 1);
        pA += __shfl_xor_sync(0xffffffffu, pA, 2);
        pB += __shfl_xor_sync(0xffffffffu, pB, 1);
        pB += __shfl_xor_sync(0xffffffffu, pB, 2);
        if (tig == 0) {
            if (v0) out[e0] = pA + b2v;
            if (v1) out[e1] = pB + b2v;
        }
        __syncthreads();
    }
}

extern "C" void kernel_launch(void* const* d_in, const int* in_sizes, int n_in,
                              void* d_out, int out_size) {
    const float* xs = (const float*)d_in[0];
    const int* ei = (const int*)d_in[1];            // int32 (JAX x64 disabled)
    const float* ea = (const float*)d_in[2];
    const float* init_w = (const float*)d_in[3];
    const float* w_ih = (const float*)d_in[4];
    const float* w_hh = (const float*)d_in[5];
    const float* b_ih = (const float*)d_in[6];
    const float* b_hh = (const float*)d_in[7];
    const float* w1 = (const float*)d_in[8];
    const float* b1 = (const float*)d_in[9];
    const float* w2 = (const float*)d_in[10];
    const float* b2 = (const float*)d_in[11];
    float* out = (float*)d_out;

    int N = in_sizes[0] / (5 * 64);
    int E = in_sizes[1] / 2;

    // k1: LSTM + in-degree histogram + x->fp16 convert (heterogeneous grid)
    int DEGB = (E + 255) / 256;
    int CVTB = (N * 64 / 8 + 255) / 256;
    lstm_deg_cvt_kernel<<<64 + DEGB + CVTB, 256>>>(init_w, w_ih, w_hh, b_ih, b_hh,
                                                   ei, xs + (size_t)4 * N * 64, N, E, DEGB);
    // k2: fp16 scatter (edges + self loops), v4.f16x2 vector reductions
    int items = E + N;
    scatter_xh_kernel<<<(items * 8 + 255) / 256, 256>>>(ei, N, E);
    // k3: tensor-core triple GEMM (128 rows/block)
    gemm_AB_mma_kernel<<<(N + 127) / 128, 256>>>(w1, N);
    // k4: per-edge MLP via tensor cores (PROFILED slot #4) + tail zeroing
    int EB = (E + ECHUNK - 1) / ECHUNK;
    int ZB = (N * 8 + 255) / 256;
    edge_mlp_zero_kernel<<<EB + ZB, 256>>>(ei, ea, w1, b1, w2, b2, out, E, N, EB);
}